// round 7
// baseline (speedup 1.0000x reference)
#include <cuda_runtime.h>
#include <cuda_bf16.h>
#include <math.h>
#include <stdint.h>

#define DMODEL 3072
#define NHEAD  24
#define HD     128
#define LQ     1280     // 256 txt + 1024 img queries
#define SKV    4352     // 256 txt + 1024 den + 3072 cached
#define STXT   256

// ---------------- scratch (device globals: allocation-free) ----------------
__device__ float g_Q[(size_t)LQ  * DMODEL];
__device__ float g_K[(size_t)SKV * DMODEL];
__device__ float g_V[(size_t)SKV * DMODEL];

// bf16 hi/lo split buffers
#define WELEMS ((size_t)DMODEL * DMODEL)
__device__ __nv_bfloat16 g_WhT[8 * WELEMS];   // transposed [N][K], hi
__device__ __nv_bfloat16 g_WlT[8 * WELEMS];   // transposed [N][K], lo
__device__ __nv_bfloat16 g_Ah[(size_t)LQ * DMODEL];   // act hi / Q hi / O hi
__device__ __nv_bfloat16 g_Al[(size_t)LQ * DMODEL];   // act lo / Q lo / O lo
__device__ __nv_bfloat16 g_Eh[(size_t)STXT * DMODEL];
__device__ __nv_bfloat16 g_El[(size_t)STXT * DMODEL];
__device__ __nv_bfloat16 g_Kh[(size_t)SKV * DMODEL];
__device__ __nv_bfloat16 g_Kl[(size_t)SKV * DMODEL];
__device__ __nv_bfloat16 g_Vh[(size_t)SKV * DMODEL];
__device__ __nv_bfloat16 g_Vl[(size_t)SKV * DMODEL];

// ---------------- PTX helpers -----------------------------------------------
__device__ __forceinline__ void cp_async16(unsigned dst, const void* src) {
    asm volatile("cp.async.cg.shared.global [%0], [%1], 16;" :: "r"(dst), "l"(src));
}
__device__ __forceinline__ void cp_commit() {
    asm volatile("cp.async.commit_group;");
}
template<int N> __device__ __forceinline__ void cp_wait() {
    asm volatile("cp.async.wait_group %0;" :: "n"(N));
}
__device__ __forceinline__ uint32_t smem_u32(const void* p) {
    uint32_t a;
    asm("{ .reg .u64 t; cvta.to.shared.u64 t, %1; cvt.u32.u64 %0, t; }" : "=r"(a) : "l"(p));
    return a;
}

#define LDSM_X4(r0, r1, r2, r3, addr)                                           \
    asm volatile("ldmatrix.sync.aligned.m8n8.x4.shared.b16 {%0,%1,%2,%3}, [%4];" \
        : "=r"(r0), "=r"(r1), "=r"(r2), "=r"(r3) : "r"(addr))

#define LDSM_X4_T(r0, r1, r2, r3, addr)                                         \
    asm volatile("ldmatrix.sync.aligned.m8n8.x4.trans.shared.b16 {%0,%1,%2,%3}, [%4];" \
        : "=r"(r0), "=r"(r1), "=r"(r2), "=r"(r3) : "r"(addr))

#define MMA16816(d, a0, a1, a2, a3, b0, b1)                                     \
    asm volatile("mma.sync.aligned.m16n8k16.row.col.f32.bf16.bf16.f32 "         \
        "{%0,%1,%2,%3},{%4,%5,%6,%7},{%8,%9},{%0,%1,%2,%3};"                    \
        : "+f"((d)[0]), "+f"((d)[1]), "+f"((d)[2]), "+f"((d)[3])                \
        : "r"(a0), "r"(a1), "r"(a2), "r"(a3), "r"(b0), "r"(b1))

__device__ __forceinline__ uint32_t packbf(float lo, float hi) {
    uint32_t r;
    asm("cvt.rn.bf16x2.f32 %0, %1, %2;" : "=r"(r) : "f"(hi), "f"(lo));
    return r;
}
__device__ __forceinline__ float bfhi(float x) {
    return __bfloat162float(__float2bfloat16(x));
}

// ---------------- conversion kernels ----------------------------------------
__global__ void convert_hl(const float4* __restrict__ X,
                           __nv_bfloat162* __restrict__ H,
                           __nv_bfloat162* __restrict__ L, int n4)
{
    int i = blockIdx.x * 256 + threadIdx.x;
    if (i >= n4) return;
    float4 v = X[i];
    __nv_bfloat16 h0 = __float2bfloat16(v.x);
    __nv_bfloat16 h1 = __float2bfloat16(v.y);
    __nv_bfloat16 h2 = __float2bfloat16(v.z);
    __nv_bfloat16 h3 = __float2bfloat16(v.w);
    __nv_bfloat16 l0 = __float2bfloat16(v.x - __bfloat162float(h0));
    __nv_bfloat16 l1 = __float2bfloat16(v.y - __bfloat162float(h1));
    __nv_bfloat16 l2 = __float2bfloat16(v.z - __bfloat162float(h2));
    __nv_bfloat16 l3 = __float2bfloat16(v.w - __bfloat162float(h3));
    H[2 * i]     = __nv_bfloat162(h0, h1);
    H[2 * i + 1] = __nv_bfloat162(h2, h3);
    L[2 * i]     = __nv_bfloat162(l0, l1);
    L[2 * i + 1] = __nv_bfloat162(l2, l3);
}

// split + transpose 8 weight matrices: W[K][N] fp32 -> WhT/WlT[N][K] bf16
struct WSrc { const float* p[8]; };

__global__ void convert_hl_T(WSrc ws, __nv_bfloat16* __restrict__ Ht,
                             __nv_bfloat16* __restrict__ Lt)
{
    __shared__ float tile[32][33];
    const int mtx = blockIdx.z;
    const float* __restrict__ W = ws.p[mtx];
    const size_t base = (size_t)mtx * WELEMS;
    const int tx = threadIdx.x;
    const int ty = threadIdx.y;
    const int n0 = blockIdx.x * 32;
    const int k0 = blockIdx.y * 32;
#pragma unroll
    for (int i = 0; i < 4; i++)
        tile[ty + 8 * i][tx] = W[(size_t)(k0 + ty + 8 * i) * DMODEL + n0 + tx];
    __syncthreads();
#pragma unroll
    for (int i = 0; i < 4; i++) {
        float x = tile[tx][ty + 8 * i];
        __nv_bfloat16 h = __float2bfloat16(x);
        __nv_bfloat16 l = __float2bfloat16(x - __bfloat162float(h));
        size_t ofs = base + (size_t)(n0 + ty + 8 * i) * DMODEL + k0 + tx;
        Ht[ofs] = h;
        Lt[ofs] = l;
    }
}

// ---------------- mma.sync bf16 hi/lo GEMM v2 (128x256 tile) ------------------
// C[z] = A[z][Mz x 3072] @ W[z][3072 x 3072] + b[z].
// CTA 128x256, BK=32, 8 warps (2x4), warp tile 64x64 of m16n8k16.
struct TGemmSet {
    const __nv_bfloat16 *ah[6], *al[6];
    const __nv_bfloat16 *wh[6], *wl[6];
    const float* b[6];
    float* c[6];
    int ny[6];
};

#define MG_A_SUB    (128 * 40)               // elems (one of Ah/Al)
#define MG_B_SUB    (256 * 40)
#define MG_STAGE_ELEMS (2 * MG_A_SUB + 2 * MG_B_SUB)   // 30720
#define MG_STAGE_BYTES (MG_STAGE_ELEMS * 2)             // 61440
#define MG_SMEM     (2 * MG_STAGE_BYTES)                // 122880

__device__ __forceinline__ void mg_load_stage(
    uint32_t sb, int stage,
    const __nv_bfloat16* __restrict__ Ah, const __nv_bfloat16* __restrict__ Al,
    const __nv_bfloat16* __restrict__ Wh, const __nv_bfloat16* __restrict__ Wl,
    int m0, int n0, int k0, int t)
{
    const uint32_t s0 = sb + stage * MG_STAGE_BYTES;
#pragma unroll
    for (int c = t; c < 512; c += 256) {
        const int row = c >> 2;
        const int ch  = (c & 3) * 8;
        const uint32_t d = s0 + (row * 40 + ch) * 2;
        const size_t ga = (size_t)(m0 + row) * DMODEL + k0 + ch;
        cp_async16(d,                  Ah + ga);
        cp_async16(d + MG_A_SUB * 2,   Al + ga);
    }
#pragma unroll
    for (int c = t; c < 1024; c += 256) {
        const int row = c >> 2;
        const int ch  = (c & 3) * 8;
        const uint32_t d = s0 + 4 * MG_A_SUB + (row * 40 + ch) * 2;
        const size_t gb = (size_t)(n0 + row) * DMODEL + k0 + ch;
        cp_async16(d,                  Wh + gb);
        cp_async16(d + MG_B_SUB * 2,   Wl + gb);
    }
    cp_commit();
}

__global__ __launch_bounds__(256, 1) void mma_gemm(TGemmSet gs)
{
    extern __shared__ __align__(128) __nv_bfloat16 smg[];
    const uint32_t sb = smem_u32(smg);

    const int z = blockIdx.z;
    if (blockIdx.y >= gs.ny[z]) return;
    const __nv_bfloat16* __restrict__ Ah = gs.ah[z];
    const __nv_bfloat16* __restrict__ Al = gs.al[z];
    const __nv_bfloat16* __restrict__ Wh = gs.wh[z];
    const __nv_bfloat16* __restrict__ Wl = gs.wl[z];
    const float* __restrict__ bias = gs.b[z];
    float* __restrict__ C = gs.c[z];

    const int t    = threadIdx.x;
    const int wid  = t >> 5;
    const int lane = t & 31;
    const int wm   = wid >> 2;        // 0..1 -> rows [wm*64, +64)
    const int wn   = wid & 3;         // 0..3 -> cols [wn*64, +64)
    const int m0   = blockIdx.y * 128;
    const int n0   = blockIdx.x * 256;

    const int mat = lane >> 3, r = lane & 7;
    int aOff[4], bOff[4];
#pragma unroll
    for (int i = 0; i < 4; i++)
        aOff[i] = (wm * 64 + 16 * i + (mat & 1) * 8 + r) * 40 + (mat >> 1) * 8;
#pragma unroll
    for (int p = 0; p < 4; p++)
        bOff[p] = (wn * 64 + 16 * p + (mat >> 1) * 8 + r) * 40 + (mat & 1) * 8;

    float acc[4][8][4];
#pragma unroll
    for (int i = 0; i < 4; i++)
#pragma unroll
        for (int j = 0; j < 8; j++)
#pragma unroll
            for (int q = 0; q < 4; q++) acc[i][j][q] = 0.f;

    const int NS = DMODEL / 32;
    mg_load_stage(sb, 0, Ah, Al, Wh, Wl, m0, n0, 0,  t);
    mg_load_stage(sb, 1, Ah, Al, Wh, Wl, m0, n0, 32, t);

    const uint32_t aBase = sb;
    const uint32_t bBase = sb + 4 * MG_A_SUB;

    for (int s = 0; s < NS; s++) {
        if (s + 1 < NS) cp_wait<1>(); else cp_wait<0>();
        __syncthreads();
        const uint32_t so = (s & 1) * MG_STAGE_BYTES;

#pragma unroll
        for (int ks = 0; ks < 2; ks++) {
            const int ke = ks * 16;
            uint32_t ah[4][4], al[4][4], bh[4][4], bl[4][4];
#pragma unroll
            for (int i = 0; i < 4; i++) {
                LDSM_X4(ah[i][0], ah[i][1], ah[i][2], ah[i][3],
                        aBase + so + (aOff[i] + ke) * 2);
                LDSM_X4(al[i][0], al[i][1], al[i][2], al[i][3],
                        aBase + so + MG_A_SUB * 2 + (aOff[i] + ke) * 2);
            }
#pragma unroll
            for (int p = 0; p < 4; p++) {
                LDSM_X4(bh[p][0], bh[p][1], bh[p][2], bh[p][3],
                        bBase + so + (bOff[p] + ke) * 2);
                LDSM_X4(bl[p][0], bl[p][1], bl[p][2], bl[p][3],
                        bBase + so + MG_B_SUB * 2 + (bOff[p] + ke) * 2);
            }
#pragma unroll
            for (int i = 0; i < 4; i++)
#pragma unroll
                for (int j = 0; j < 8; j++) {
                    const int p = j >> 1, q = (j & 1) * 2;
                    MMA16816(acc[i][j], ah[i][0], ah[i][1], ah[i][2], ah[i][3],
                             bh[p][q], bh[p][q + 1]);
                    MMA16816(acc[i][j], ah[i][0], ah[i][1], ah[i][2], ah[i][3],
                             bl[p][q], bl[p][q + 1]);
                    MMA16816(acc[i][j], al[i][0], al[i][1], al[i][2], al[i][3],
                             bh[p][q], bh[p][q + 1]);
                }
        }
        __syncthreads();
        if (s + 2 < NS)
            mg_load_stage(sb, s & 1, Ah, Al, Wh, Wl, m0, n0, (s + 2) * 32, t);
    }

    const int r4 = lane >> 2;
    const int c2 = (lane & 3) * 2;
#pragma unroll
    for (int i = 0; i < 4; i++) {
        const int grow = m0 + wm * 64 + 16 * i + r4;
#pragma unroll
        for (int j = 0; j < 8; j++) {
            const int gcol = n0 + wn * 64 + 8 * j + c2;
            const float b0 = bias[gcol], b1 = bias[gcol + 1];
            float2 v0, v1;
            v0.x = acc[i][j][0] + b0; v0.y = acc[i][j][1] + b1;
            v1.x = acc[i][j][2] + b0; v1.y = acc[i][j][3] + b1;
            *(float2*)(C + (size_t)grow * DMODEL + gcol)       = v0;
            *(float2*)(C + (size_t)(grow + 8) * DMODEL + gcol) = v1;
        }
    }
}

// ---------------- RMSNorm + RoPE -> bf16 hi/lo --------------------------------
__global__ void normrope_hl(
    const float* __restrict__ X, int rows,
    const float* __restrict__ w_txt, const float* __restrict__ w_img,
    const float* __restrict__ tcos, const float* __restrict__ tsin,
    const float* __restrict__ icos, const float* __restrict__ isin,
    float outscale,
    __nv_bfloat162* __restrict__ H, __nv_bfloat162* __restrict__ L)
{
    const int id   = blockIdx.x * blockDim.y + threadIdx.y;
    const int lane = threadIdx.x;
    if (id >= rows * NHEAD) return;
    const int row = id / NHEAD;
    const int h   = id % NHEAD;

    const float2* p2 = (const float2*)(X + (size_t)row * DMODEL + h * HD);
    float2 v0 = p2[lane];
    float2 v1 = p2[lane + 32];

    float ss = v0.x * v0.x + v0.y * v0.y + v1.x * v1.x + v1.y * v1.y;
#pragma unroll
    for (int o = 16; o > 0; o >>= 1) ss += __shfl_xor_sync(0xffffffffu, ss, o);
    const float rms = rsqrtf(ss * (1.0f / 128.0f) + 1e-6f);

    const float *w, *cT, *sT;
    if (row < STXT) { w = w_txt; cT = tcos + (size_t)row * 64;          sT = tsin + (size_t)row * 64; }
    else            { w = w_img; cT = icos + (size_t)(row - STXT) * 64; sT = isin + (size_t)(row - STXT) * 64; }

    const size_t ob = ((size_t)row * DMODEL + h * HD) / 2;
#pragma unroll
    for (int half = 0; half < 2; half++) {
        const int p = lane + 32 * half;
        const float2 v = half ? v1 : v0;
        float c = cT[p], s = sT[p];
        float yr = v.x * rms * w[2 * p];
        float yi = v.y * rms * w[2 * p + 1];
        float o0 = (yr * c - yi * s) * outscale;
        float o1 = (yr * s + yi * c) * outscale;
        __nv_bfloat16 h0 = __float2bfloat16(o0);
        __nv_bfloat16 h1 = __float2bfloat16(o1);
        __nv_bfloat16 l0 = __float2bfloat16(o0 - __bfloat162float(h0));
        __nv_bfloat16 l1 = __float2bfloat16(o1 - __bfloat162float(h1));
        H[ob + p] = __nv_bfloat162(h0, h1);
        L[ob + p] = __nv_bfloat162(l0, l1);
    }
}

// ---------------- Flash attention v3: bf16 hi/lo mma.sync --------------------
// 128q x 64kv tiles, 8 warps (16 q rows each), online softmax in registers.
#define AST     136                 // bf16 row stride (272B; 272%128=16 -> conflict-free)
#define AMAT    (64 * AST)          // elems per matrix
#define ASTB    (AMAT * 2)          // bytes per matrix (17408)
#define ASTAGEB (4 * ASTB)          // Kh|Kl|Vh|Vl stage bytes (69632)
#define ATTN3_SMEM (2 * ASTAGEB + 1024)
#define ATHREADS 256

__global__ __launch_bounds__(ATHREADS) void attn3(
    const __nv_bfloat16* __restrict__ Qh, const __nv_bfloat16* __restrict__ Ql,
    const __nv_bfloat16* __restrict__ Kh, const __nv_bfloat16* __restrict__ Kl,
    const __nv_bfloat16* __restrict__ Vh, const __nv_bfloat16* __restrict__ Vl,
    const int* __restrict__ mask,
    __nv_bfloat16* __restrict__ Oh, __nv_bfloat16* __restrict__ Ol)
{
    extern __shared__ __align__(16) char sm3[];
    const uint32_t sbase = smem_u32(sm3);
    float* mb = (float*)(sm3 + 2 * ASTAGEB);

    const int t    = threadIdx.x;
    const int wid  = t >> 5;       // 0..7 -> q rows [wid*16, wid*16+16)
    const int lane = t & 31;
    const int h    = blockIdx.y;
    const int q0   = blockIdx.x * 128;
    const int hcol = h * HD;

    const int gr = lane >> 2, ct = lane & 3;
    const int mat = lane >> 3, r = lane & 7;
    const int bRow = ((mat >> 1) << 3) + r;   // K (non-trans) ldmatrix row sel
    const int bCol = (mat & 1) << 3;
    const int vRow = ((mat & 1) << 3) + r;    // V (trans) ldmatrix row sel
    const int vCol = (mat >> 1) << 3;

    // mask bias
    for (int i = t; i < STXT; i += ATHREADS)
        mb[i] = (mask[i] == 0) ? -1e30f : 0.f;

    // Q fragments (registers, loaded once)
    uint32_t qh[8][4], ql[8][4];
    {
        const size_t r0 = (size_t)(q0 + wid * 16 + gr) * DMODEL + hcol;
        const size_t r1 = r0 + 8 * DMODEL;
#pragma unroll
        for (int c = 0; c < 8; c++) {
            const int col = 16 * c + 2 * ct;
            qh[c][0] = *(const uint32_t*)(Qh + r0 + col);
            qh[c][1] = *(const uint32_t*)(Qh + r1 + col);
            qh[c][2] = *(const uint32_t*)(Qh + r0 + col + 8);
            qh[c][3] = *(const uint32_t*)(Qh + r1 + col + 8);
            ql[c][0] = *(const uint32_t*)(Ql + r0 + col);
            ql[c][1] = *(const uint32_t*)(Ql + r1 + col);
            ql[c][2] = *(const uint32_t*)(Ql + r0 + col + 8);
            ql[c][3] = *(const uint32_t*)(Ql + r1 + col + 8);
        }
    }

    float o[16][4];
#pragma unroll
    for (int j = 0; j < 16; j++)
#pragma unroll
        for (int e = 0; e < 4; e++) o[j][e] = 0.f;
    float m0 = -INFINITY, m1 = -INFINITY, l0 = 0.f, l1 = 0.f;

#define ISSUE_KV3(st, kb)                                                         \
    {                                                                             \
        _Pragma("unroll")                                                         \
        for (int c = t; c < 4096; c += ATHREADS) {                                \
            const int mtx = c >> 10;                                              \
            const int rem = c & 1023;                                             \
            const int row = rem >> 4;                                             \
            const int ch  = (rem & 15) * 8;                                       \
            const __nv_bfloat16* src = (mtx == 0) ? Kh : (mtx == 1) ? Kl          \
                                     : (mtx == 2) ? Vh : Vl;                      \
            cp_async16(sbase + (st) * ASTAGEB + mtx * ASTB + (row * AST + ch) * 2,\
                       src + (size_t)((kb) + row) * DMODEL + hcol + ch);          \
        }                                                                         \
        cp_commit();                                                              \
    }

    const int NT = SKV / 64;   // 68
    ISSUE_KV3(0, 0)

    for (int kt = 0; kt < NT; kt++) {
        const int kb = kt * 64;
        if (kt + 1 < NT) {
            ISSUE_KV3((kt + 1) & 1, (kt + 1) * 64)
            cp_wait<1>();
        } else {
            cp_wait<0>();
        }
        __syncthreads();
        const uint32_t stg = sbase + (kt & 1) * ASTAGEB;

        // ---- QK ----
        float s[8][4];
#pragma unroll
        for (int j = 0; j < 8; j++)
#pragma unroll
            for (int e = 0; e < 4; e++) s[j][e] = 0.f;

#pragma unroll
        for (int c = 0; c < 8; c++) {
#pragma unroll
            for (int g2 = 0; g2 < 4; g2++) {
                uint32_t kh0, kh1, kh2, kh3, kl0, kl1, kl2, kl3;
                const uint32_t a = stg +
                    (((g2 * 16 + bRow) * AST + 16 * c + bCol) << 1);
                LDSM_X4(kh0, kh1, kh2, kh3, a);
                LDSM_X4(kl0, kl1, kl2, kl3, a + ASTB);
                MMA16816(s[2 * g2], qh[c][0], qh[c][1], qh[c][2], qh[c][3], kh0, kh1);
                MMA16816(s[2 * g2], qh[c][0], qh[c][1], qh[c][2], qh[c][3], kl0, kl1);
                MMA16816(s[2 * g2], ql[c][0], ql[c][1], ql[c][2], ql[c][3], kh0, kh1);
                MMA16816(s[2 * g2 + 1], qh[c][0], qh[c][1], qh[c][2], qh[c][3], kh2, kh3);
                MMA16816(s[2 * g2 + 1], qh[c][0], qh[c][1], qh[c][2], qh[c][3], kl2, kl3);
                MMA16816(s[2 * g2 + 1], ql[c][0], ql[c][1], ql[c][2], ql[c][3], kh2, kh3);
            }
        }

        if (kb < STXT) {
#pragma unroll
            for (int j = 0; j < 8; j++) {
                const int col = kb + 8 * j + 2 * ct;
                const float b0 = mb[col], b1 = mb[col + 1];
                s[j][0] += b0; s[j][1] += b1;
                s[j][2] += b0; s[j][3] += b1;
            }
        }

        // ---- online softmax (register-resident) ----
        float tm0 = -1e30f, tm1 = -1e30f;
#pragma unroll
        for (int j = 0; j < 8; j++) {
            tm0 = fmaxf(tm0, fmaxf(s[j][0], s[j][1]));
            tm1 = fmaxf(tm1, fmaxf(s[j][2], s[j][3]));
        }
        tm0 = fmaxf(tm0, __shfl_xor_sync(0xffffffffu, tm0, 1));
        tm0 = fmaxf(tm0, __shfl_xor_sync(0xffffffffu, tm0, 2));
        tm1 = fmaxf(tm1, __shfl_xor_sync(0xffffffffu, tm1, 1));
        tm1 = fmaxf(tm1, __shfl_xor_sync(0xffffffffu, tm1, 2));
        const float mn0 = fmaxf(m0, tm0), mn1 = fmaxf(m1, tm1);
        const float c0 = __expf(m0 - mn0), c1 = __expf(m1 - mn1);
        l0 *= c0; l1 *= c1;
#pragma unroll
        for (int j = 0; j < 16; j++) {
            o[j][0] *= c0; o[j][1] *= c0;
            o[j][2] *= c1; o[j][3] *= c1;
        }
        float s0 = 0.f, s1 = 0.f;
#pragma unroll
        for (int j = 0; j < 8; j++) {
            s[j][0] = __expf(s[j][0] - mn0);
            s[j][1] = __expf(s[j][1] - mn0);
            s[j][2] = __expf(s[j][2] - mn1);
            s[j][3] = __expf(s[j][3] - mn1);
            s0 += s[j][0] + s[j][1];
            s1 += s[j][2] + s[j][3];
        }
        s0 += __shfl_xor_sync(0xffffffffu, s0, 1);
        s0 += __shfl_xor_sync(0xffffffffu, s0, 2);
        s1 += __shfl_xor_sync(0xffffffffu, s1, 1);
        s1 += __shfl_xor_sync(0xffffffffu, s1, 2);
        l0 += s0; l1 += s1;
        m0 = mn0; m1 = mn1;

        // ---- pack P to bf16 hi/lo A-fragments ----
        uint32_t ph[4][4], pl[4][4];
#pragma unroll
        for (int mm = 0; mm < 4; mm++) {
            const int j0 = 2 * mm, j1 = 2 * mm + 1;
            ph[mm][0] = packbf(s[j0][0], s[j0][1]);
            ph[mm][1] = packbf(s[j0][2], s[j0][3]);
            ph[mm][2] = packbf(s[j1][0], s[j1][1]);
            ph[mm][3] = packbf(s[j1][2], s[j1][3]);
            pl[mm][0] = packbf(s[j0][0] - bfhi(s[j0][0]), s[j0][1] - bfhi(s[j0][1]));
            pl[mm][1] = packbf(s[j0][2] - bfhi(s[j0][2]), s[j0][3] - bfhi(s[j0][3]));
            pl[mm][2] = packbf(s[j1][0] - bfhi(s[j1][0]), s[j1][1] - bfhi(s[j1][1]));
            pl[mm][3] = packbf(s[j1][2] - bfhi(s[j1][2]), s[j1][3] - bfhi(s[j1][3]));
        }

        // ---- PV ----
#pragma unroll
        for (int mm = 0; mm < 4; mm++) {
#pragma unroll
            for (int g = 0; g < 8; g++) {
                uint32_t vh0, vh1, vh2, vh3, vl0, vl1, vl2, vl3;
                const uint32_t a = stg + 2 * ASTB +
                    (((16 * mm + vRow) * AST + 16 * g + vCol) << 1);
                LDSM_X4_T(vh0, vh1, vh2, vh3, a);
                LDSM_X4_T(vl0, vl1, vl2, vl3, a + ASTB);
                MMA16816(o[2 * g], ph[mm][0], ph[mm][1], ph[mm][2], ph[mm][3], vh0, vh1);
                MMA16816(o[2 * g], ph[mm][0], ph[mm][1], ph[mm][2], ph[mm][3], vl0, vl1);
                MMA16816(o[2 * g], pl[mm][0], pl[mm][1], pl[mm][2], pl[mm][3], vh0, vh1);
                MMA16816(o[2 * g + 1], ph[mm][0], ph[mm][1], ph[mm][2], ph[mm][3], vh2, vh3);
                MMA16816(o[2 * g + 1], ph[mm][0], ph[mm][1], ph[mm][2], ph[mm][3], vl2, vl3);
                MMA16816(o[2 * g + 1], pl[mm][0], pl[mm][1], pl[mm][2], pl[mm][3], vh2, vh3);
            }
        }
        __syncthreads();
    }
#undef ISSUE_KV3

    // ---- epilogue: O /= l, write bf16 hi/lo ----
    const float inv0 = 1.0f / l0, inv1 = 1.0f / l1;
    const size_t r0 = (size_t)(q0 + wid * 16 + gr) * DMODEL + hcol;
    const size_t r1 = r0 + 8 * DMODEL;
#pragma unroll
    for (int j = 0; j < 16; j++) {
        const int col = 8 * j + 2 * ct;
        const float f0 = o[j][0] * inv0, f1 = o[j][1] * inv0;
        const float f2 = o[j][2] * inv1, f3 = o[j][3] * inv1;
        *(uint32_t*)(Oh + r0 + col) = packbf(bfhi(f0), bfhi(f1));
        *(uint32_t*)(Ol + r0 + col) = packbf(f0 - bfhi(f0), f1 - bfhi(f1));
        *(uint32_t*)(Oh + r1 + col) = packbf(bfhi(f2), bfhi(f3));
        *(uint32_t*)(Ol + r1 + col) = packbf(f2 - bfhi(f2), f3 - bfhi(f3));
    }
}

// ---------------- launch -----------------------------------------------------
extern "C" void kernel_launch(void* const* d_in, const int* in_sizes, int n_in,
                              void* d_out, int out_size)
{
    const float* hidden = (const float*)d_in[0];
    const float* enc    = (const float*)d_in[1];
    const int*   mask   = (const int*)  d_in[2];
    const float* ck     = (const float*)d_in[3];
    const float* cv     = (const float*)d_in[4];
    const float* icos   = (const float*)d_in[5];
    const float* isin   = (const float*)d_in[6];
    const float* tcos   = (const float*)d_in[7];
    const float* tsin   = (const float*)d_in[8];
    const float* Wq     = (const float*)d_in[9];
    const float* bq     = (const float*)d_in[10];
    const float* Wk     = (const float*)d_in[11];
    const float* bk     = (const float*)d_in[12];
    const float* Wv     = (const float*)d_in[13];
    const float* bv     = (const float*)d_in[14];
    const float* Wq_add = (const float*)d_in[15];
    const float* bq_add = (const float*)d_in[16];
    const float* Wk_add = (const float*)d_in[17];
    const float* bk_add = (const float*)d_in[18];
    const float* Wv_add = (const float*)d_in[19];
    const float* bv_add = (const float*)d_in[20];
    const float* nqw    = (const float*)d_in[21];
    const float* nkw    = (const float*)d_in[22];
    const float* naqw   = (const float*)d_in[23];
    const float* nakw   = (const float*)d_in[24];
    const float* Wo     = (const float*)d_in[25];
    const float* bo     = (const float*)d_in[26];
    const float* Wo_add = (const float*)d_in[27];
    const float* bo_add = (const float*)d_in[28];
    float* out = (float*)d_out;

    float *Qb, *Kb, *Vb;
    cudaGetSymbolAddress((void**)&Qb, g_Q);
    cudaGetSymbolAddress((void**)&Kb, g_K);
    cudaGetSymbolAddress((void**)&Vb, g_V);
    __nv_bfloat16 *WhT, *WlT, *Ah, *Al, *Eh, *El, *Khb, *Klb, *Vhb, *Vlb;
    cudaGetSymbolAddress((void**)&WhT, g_WhT);
    cudaGetSymbolAddress((void**)&WlT, g_WlT);
    cudaGetSymbolAddress((void**)&Ah, g_Ah);
    cudaGetSymbolAddress((void**)&Al, g_Al);
    cudaGetSymbolAddress((void**)&Eh, g_Eh);
    cudaGetSymbolAddress((void**)&El, g_El);
    cudaGetSymbolAddress((void**)&Khb, g_Kh);
    cudaGetSymbolAddress((void**)&Klb, g_Kl);
    cudaGetSymbolAddress((void**)&Vhb, g_Vh);
    cudaGetSymbolAddress((void**)&Vlb, g_Vl);

    cudaFuncSetAttribute(mma_gemm, cudaFuncAttributeMaxDynamicSharedMemorySize,
                         MG_SMEM);
    cudaFuncSetAttribute(attn3, cudaFuncAttributeMaxDynamicSharedMemorySize,
                         ATTN3_SMEM);

    // cached K -> tail of fp32 K buffer (rows 1280..4351); V handled via convert
    cudaMemcpyAsync(Kb + (size_t)1280 * DMODEL, ck,
                    (size_t)3072 * DMODEL * sizeof(float), cudaMemcpyDeviceToDevice);

    // weight split+transpose
    {
        WSrc ws;
        ws.p[0] = Wq;     ws.p[1] = Wk;     ws.p[2] = Wv;
        ws.p[3] = Wq_add; ws.p[4] = Wk_add; ws.p[5] = Wv_add;
        ws.p[6] = Wo;     ws.p[7] = Wo_add;
        convert_hl_T<<<dim3(96, 96, 8), dim3(32, 8)>>>(ws, WhT, WlT);
    }
    // activation splits
    {
        int n4h = 1024 * DMODEL / 4;
        convert_hl<<<(n4h + 255) / 256, 256>>>((const float4*)hidden,
                                               (__nv_bfloat162*)Ah, (__nv_bfloat162*)Al, n4h);
        int n4e = STXT * DMODEL / 4;
        convert_hl<<<(n4e + 255) / 256, 256>>>((const float4*)enc,
                                               (__nv_bfloat162*)Eh, (__nv_bfloat162*)El, n4e);
    }

    // QKV projections: ONE launch, z=0..2 img (8 y-tiles), z=3..5 txt (2 y-tiles)
    {
        TGemmSet g;
        for (int z = 0; z < 3; z++) {
            g.ah[z] = Ah; g.al[z] = Al;
            g.wh[z] = WhT + (size_t)z * WELEMS;
            g.wl[z] = WlT + (size_t)z * WELEMS;
            g.ny[z] = 8;
            g.ah[z + 3] = Eh; g.al[z + 3] = El;
            g.wh[z + 3] = WhT + (size_t)(z + 3) * WELEMS;
            g.wl[z + 3] = WlT + (size_t)(z + 3) * WELEMS;
            g.ny[z + 3] = 2;
        }
        g.b[0] = bq; g.b[1] = bk; g.b[2] = bv;
        g.b[3] = bq_add; g.b[4] = bk_add; g.b[5] = bv_add;
        g.c[0] = Qb + (size_t)256 * DMODEL;
        g.c[1] = Kb + (size_t)256 * DMODEL;
        g.c[2] = Vb + (size_t)256 * DMODEL;
        g.c[3] = Qb; g.c[4] = Kb; g.c[5] = Vb;
        mma_gemm<<<dim3(12, 8, 6), 256, MG_SMEM>>>(g);
    }

    // RMSNorm + RoPE -> bf16 hi/lo (Q into Ah/Al — GEMM inputs are dead now)
    const float qscale = 0.08838834764831845f; // 1/sqrt(128)
    dim3 nb(32, 8);
    {
        int tot = LQ * NHEAD;
        normrope_hl<<<(tot + 7) / 8, nb>>>(Qb, LQ, naqw, nqw,
                                           tcos, tsin, icos, isin, qscale,
                                           (__nv_bfloat162*)Ah, (__nv_bfloat162*)Al);
    }
    {
        int tot = SKV * NHEAD;
        normrope_hl<<<(tot + 7) / 8, nb>>>(Kb, SKV, nakw, nkw,
                                           tcos, tsin, icos, isin, 1.0f,
                                           (__nv_bfloat162*)Khb, (__nv_bfloat162*)Klb);
    }
    // V hi/lo: projected rows 0..1279 + cached rows 1280..4351
    {
        int n4v = 1280 * DMODEL / 4;
        convert_hl<<<(n4v + 255) / 256, 256>>>((const float4*)Vb,
                                               (__nv_bfloat162*)Vhb, (__nv_bfloat162*)Vlb, n4v);
        int n4c = 3072 * DMODEL / 4;
        convert_hl<<<(n4c + 255) / 256, 256>>>((const float4*)cv,
                                               (__nv_bfloat162*)(Vhb + (size_t)1280 * DMODEL),
                                               (__nv_bfloat162*)(Vlb + (size_t)1280 * DMODEL), n4c);
    }

    // attention: reads Q from Ah/Al, writes O (bf16 hi/lo) back into Ah/Al
    attn3<<<dim3(LQ / 128, NHEAD), ATHREADS, ATTN3_SMEM>>>(
        Ah, Al, Khb, Klb, Vhb, Vlb, mask, Ah, Al);

    // output projections: ONE launch, z=0 img (8 y-tiles), z=1 txt (2 y-tiles)
    {
        TGemmSet g;
        g.ah[0] = Ah + (size_t)256 * DMODEL; g.al[0] = Al + (size_t)256 * DMODEL;
        g.wh[0] = WhT + 6 * WELEMS;          g.wl[0] = WlT + 6 * WELEMS;
        g.b[0]  = bo;                        g.c[0]  = out;
        g.ny[0] = 8;
        g.ah[1] = Ah;                        g.al[1] = Al;
        g.wh[1] = WhT + 7 * WELEMS;          g.wl[1] = WlT + 7 * WELEMS;
        g.b[1]  = bo_add;                    g.c[1]  = out + (size_t)1024 * DMODEL;
        g.ny[1] = 2;
        for (int z = 2; z < 6; z++) {
            g.ah[z] = Ah; g.al[z] = Al;
            g.wh[z] = WhT; g.wl[z] = WlT;
            g.b[z] = bo; g.c[z] = out; g.ny[z] = 0;
        }
        mma_gemm<<<dim3(12, 8, 2), 256, MG_SMEM>>>(g);
    }
}

// round 8
// speedup vs baseline: 1.1292x; 1.1292x over previous
#include <cuda_runtime.h>
#include <cuda_bf16.h>
#include <math.h>
#include <stdint.h>

#define DMODEL 3072
#define NHEAD  24
#define HD     128
#define LQ     1280     // 256 txt + 1024 img queries
#define SKV    4352     // 256 txt + 1024 den + 3072 cached
#define STXT   256

// ---------------- scratch (device globals: allocation-free) ----------------
__device__ float g_Q[(size_t)LQ * DMODEL];
__device__ float g_K[(size_t)LQ * DMODEL];   // projected K rows 0..1279 only
__device__ float g_V[(size_t)LQ * DMODEL];   // projected V rows 0..1279 only

// bf16 hi/lo split buffers
#define WELEMS ((size_t)DMODEL * DMODEL)
__device__ __nv_bfloat16 g_Wh[8 * WELEMS];   // [K][N] layout, hi
__device__ __nv_bfloat16 g_Wl[8 * WELEMS];   // [K][N] layout, lo
__device__ __nv_bfloat16 g_Ah[(size_t)LQ * DMODEL];   // act hi / Q hi / O hi
__device__ __nv_bfloat16 g_Al[(size_t)LQ * DMODEL];   // act lo / Q lo / O lo
__device__ __nv_bfloat16 g_Eh[(size_t)STXT * DMODEL];
__device__ __nv_bfloat16 g_El[(size_t)STXT * DMODEL];
__device__ __nv_bfloat16 g_Kh[(size_t)SKV * DMODEL];
__device__ __nv_bfloat16 g_Kl[(size_t)SKV * DMODEL];
__device__ __nv_bfloat16 g_Vh[(size_t)SKV * DMODEL];
__device__ __nv_bfloat16 g_Vl[(size_t)SKV * DMODEL];

// ---------------- PTX helpers -----------------------------------------------
__device__ __forceinline__ void cp_async16(unsigned dst, const void* src) {
    asm volatile("cp.async.cg.shared.global [%0], [%1], 16;" :: "r"(dst), "l"(src));
}
__device__ __forceinline__ void cp_commit() {
    asm volatile("cp.async.commit_group;");
}
template<int N> __device__ __forceinline__ void cp_wait() {
    asm volatile("cp.async.wait_group %0;" :: "n"(N));
}
__device__ __forceinline__ uint32_t smem_u32(const void* p) {
    uint32_t a;
    asm("{ .reg .u64 t; cvta.to.shared.u64 t, %1; cvt.u32.u64 %0, t; }" : "=r"(a) : "l"(p));
    return a;
}

#define LDSM_X4(r0, r1, r2, r3, addr)                                           \
    asm volatile("ldmatrix.sync.aligned.m8n8.x4.shared.b16 {%0,%1,%2,%3}, [%4];" \
        : "=r"(r0), "=r"(r1), "=r"(r2), "=r"(r3) : "r"(addr))

#define LDSM_X4_T(r0, r1, r2, r3, addr)                                         \
    asm volatile("ldmatrix.sync.aligned.m8n8.x4.trans.shared.b16 {%0,%1,%2,%3}, [%4];" \
        : "=r"(r0), "=r"(r1), "=r"(r2), "=r"(r3) : "r"(addr))

#define MMA16816(d, a0, a1, a2, a3, b0, b1)                                     \
    asm volatile("mma.sync.aligned.m16n8k16.row.col.f32.bf16.bf16.f32 "         \
        "{%0,%1,%2,%3},{%4,%5,%6,%7},{%8,%9},{%0,%1,%2,%3};"                    \
        : "+f"((d)[0]), "+f"((d)[1]), "+f"((d)[2]), "+f"((d)[3])                \
        : "r"(a0), "r"(a1), "r"(a2), "r"(a3), "r"(b0), "r"(b1))

__device__ __forceinline__ uint32_t packbf(float lo, float hi) {
    uint32_t r;
    asm("cvt.rn.bf16x2.f32 %0, %1, %2;" : "=r"(r) : "f"(hi), "f"(lo));
    return r;
}
__device__ __forceinline__ float bfhi(float x) {
    return __bfloat162float(__float2bfloat16(x));
}

// ---------------- conversion kernels ----------------------------------------
__global__ void convert_hl(const float4* __restrict__ X,
                           __nv_bfloat162* __restrict__ H,
                           __nv_bfloat162* __restrict__ L, int n4)
{
    int i = blockIdx.x * 256 + threadIdx.x;
    if (i >= n4) return;
    float4 v = X[i];
    __nv_bfloat16 h0 = __float2bfloat16(v.x);
    __nv_bfloat16 h1 = __float2bfloat16(v.y);
    __nv_bfloat16 h2 = __float2bfloat16(v.z);
    __nv_bfloat16 h3 = __float2bfloat16(v.w);
    __nv_bfloat16 l0 = __float2bfloat16(v.x - __bfloat162float(h0));
    __nv_bfloat16 l1 = __float2bfloat16(v.y - __bfloat162float(h1));
    __nv_bfloat16 l2 = __float2bfloat16(v.z - __bfloat162float(h2));
    __nv_bfloat16 l3 = __float2bfloat16(v.w - __bfloat162float(h3));
    H[2 * i]     = __nv_bfloat162(h0, h1);
    H[2 * i + 1] = __nv_bfloat162(h2, h3);
    L[2 * i]     = __nv_bfloat162(l0, l1);
    L[2 * i + 1] = __nv_bfloat162(l2, l3);
}

// elementwise hi/lo split for 8 weight matrices, native [K][N] layout
struct WSrc { const float* p[8]; };

__global__ void convert_hl8(WSrc ws, __nv_bfloat162* __restrict__ H,
                            __nv_bfloat162* __restrict__ L)
{
    const int mtx = blockIdx.y;
    const int i = blockIdx.x * 256 + threadIdx.x;       // float4 index
    const float4* __restrict__ X = (const float4*)ws.p[mtx];
    const size_t b2 = (size_t)mtx * (WELEMS / 2);
    float4 v = X[i];
    __nv_bfloat16 h0 = __float2bfloat16(v.x);
    __nv_bfloat16 h1 = __float2bfloat16(v.y);
    __nv_bfloat16 h2 = __float2bfloat16(v.z);
    __nv_bfloat16 h3 = __float2bfloat16(v.w);
    __nv_bfloat16 l0 = __float2bfloat16(v.x - __bfloat162float(h0));
    __nv_bfloat16 l1 = __float2bfloat16(v.y - __bfloat162float(h1));
    __nv_bfloat16 l2 = __float2bfloat16(v.z - __bfloat162float(h2));
    __nv_bfloat16 l3 = __float2bfloat16(v.w - __bfloat162float(h3));
    H[b2 + 2 * i]     = __nv_bfloat162(h0, h1);
    H[b2 + 2 * i + 1] = __nv_bfloat162(h2, h3);
    L[b2 + 2 * i]     = __nv_bfloat162(l0, l1);
    L[b2 + 2 * i + 1] = __nv_bfloat162(l2, l3);
}

// ---------------- mma.sync bf16 hi/lo GEMM (128x128, trans-B) ----------------
// C[z] = A[z][Mz x 3072] @ W[z][3072 x 3072] + b[z];  W stored [K][N].
// CTA 128x128, BK=32, 8 warps (2x4), warp tile 64x32 of m16n8k16.
struct TGemmSet {
    const __nv_bfloat16 *ah[6], *al[6];
    const __nv_bfloat16 *wh[6], *wl[6];
    const float* b[6];
    float* c[6];
    int ny[6];
};

#define MG_A_SUB_B  (128 * 40 * 2)          // 10240 bytes per A sub
#define MG_B_SUB_B  (32 * 136 * 2)          // 8704 bytes per B sub
#define MG_B_OFF    (2 * MG_A_SUB_B)        // 20480
#define MG_STAGE_BYTES (2 * MG_A_SUB_B + 2 * MG_B_SUB_B)   // 37888
#define MG_SMEM     (2 * MG_STAGE_BYTES)                    // 75776

__device__ __forceinline__ void mg_load_stage(
    uint32_t sb, int stage,
    const __nv_bfloat16* __restrict__ Ah, const __nv_bfloat16* __restrict__ Al,
    const __nv_bfloat16* __restrict__ Wh, const __nv_bfloat16* __restrict__ Wl,
    int m0, int n0, int k0, int t)
{
    const uint32_t s0 = sb + stage * MG_STAGE_BYTES;
    // A: [128 rows][32 k] -> smem [128][40]
#pragma unroll
    for (int c = t; c < 512; c += 256) {
        const int row = c >> 2;
        const int ch  = (c & 3) * 8;
        const uint32_t d = s0 + (row * 40 + ch) * 2;
        const size_t ga = (size_t)(m0 + row) * DMODEL + k0 + ch;
        cp_async16(d,               Ah + ga);
        cp_async16(d + MG_A_SUB_B,  Al + ga);
    }
    // B: [32 k-rows][128 n] from W[K][N] -> smem [32][136]
#pragma unroll
    for (int c = t; c < 512; c += 256) {
        const int row = c >> 4;            // 0..31 (k)
        const int ch  = (c & 15) * 8;      // 0..120 (n)
        const uint32_t d = s0 + MG_B_OFF + (row * 136 + ch) * 2;
        const size_t gb = (size_t)(k0 + row) * DMODEL + n0 + ch;
        cp_async16(d,               Wh + gb);
        cp_async16(d + MG_B_SUB_B,  Wl + gb);
    }
    cp_commit();
}

__global__ __launch_bounds__(256) void mma_gemm(TGemmSet gs)
{
    extern __shared__ __align__(128) __nv_bfloat16 smg[];
    const uint32_t sb = smem_u32(smg);

    const int z = blockIdx.z;
    if (blockIdx.y >= gs.ny[z]) return;
    const __nv_bfloat16* __restrict__ Ah = gs.ah[z];
    const __nv_bfloat16* __restrict__ Al = gs.al[z];
    const __nv_bfloat16* __restrict__ Wh = gs.wh[z];
    const __nv_bfloat16* __restrict__ Wl = gs.wl[z];
    const float* __restrict__ bias = gs.b[z];
    float* __restrict__ C = gs.c[z];

    const int t    = threadIdx.x;
    const int wid  = t >> 5;
    const int lane = t & 31;
    const int wm   = wid >> 2;        // 0..1
    const int wn   = wid & 3;         // 0..3
    const int m0   = blockIdx.y * 128;
    const int n0   = blockIdx.x * 128;

    const int mat = lane >> 3, r = lane & 7;
    int aOff[4], bOffT[2];
#pragma unroll
    for (int i = 0; i < 4; i++)
        aOff[i] = (wm * 64 + 16 * i + (mat & 1) * 8 + r) * 40 + (mat >> 1) * 8;
    {
        const int tRow = ((mat & 1) << 3) + r;   // k within 16-block
        const int tCol = (mat >> 1) << 3;        // n within 16-block
#pragma unroll
        for (int p = 0; p < 2; p++)
            bOffT[p] = tRow * 136 + wn * 32 + 16 * p + tCol;
    }

    float acc[4][4][4];
#pragma unroll
    for (int i = 0; i < 4; i++)
#pragma unroll
        for (int j = 0; j < 4; j++)
#pragma unroll
            for (int q = 0; q < 4; q++) acc[i][j][q] = 0.f;

    const int NS = DMODEL / 32;   // 96
    mg_load_stage(sb, 0, Ah, Al, Wh, Wl, m0, n0, 0,  t);
    mg_load_stage(sb, 1, Ah, Al, Wh, Wl, m0, n0, 32, t);

    for (int s = 0; s < NS; s++) {
        if (s + 1 < NS) cp_wait<1>(); else cp_wait<0>();
        __syncthreads();
        const uint32_t s0 = sb + (s & 1) * MG_STAGE_BYTES;

#pragma unroll
        for (int ks = 0; ks < 2; ks++) {
            const int ke = ks * 16;
            uint32_t ah[4][4], al[4][4], bh[2][4], bl[2][4];
#pragma unroll
            for (int i = 0; i < 4; i++) {
                LDSM_X4(ah[i][0], ah[i][1], ah[i][2], ah[i][3],
                        s0 + (aOff[i] + ke) * 2);
                LDSM_X4(al[i][0], al[i][1], al[i][2], al[i][3],
                        s0 + MG_A_SUB_B + (aOff[i] + ke) * 2);
            }
#pragma unroll
            for (int p = 0; p < 2; p++) {
                LDSM_X4_T(bh[p][0], bh[p][1], bh[p][2], bh[p][3],
                          s0 + MG_B_OFF + (bOffT[p] + ke * 136) * 2);
                LDSM_X4_T(bl[p][0], bl[p][1], bl[p][2], bl[p][3],
                          s0 + MG_B_OFF + MG_B_SUB_B + (bOffT[p] + ke * 136) * 2);
            }
#pragma unroll
            for (int i = 0; i < 4; i++)
#pragma unroll
                for (int j = 0; j < 4; j++) {
                    const int p = j >> 1, q = (j & 1) * 2;
                    MMA16816(acc[i][j], ah[i][0], ah[i][1], ah[i][2], ah[i][3],
                             bh[p][q], bh[p][q + 1]);
                    MMA16816(acc[i][j], ah[i][0], ah[i][1], ah[i][2], ah[i][3],
                             bl[p][q], bl[p][q + 1]);
                    MMA16816(acc[i][j], al[i][0], al[i][1], al[i][2], al[i][3],
                             bh[p][q], bh[p][q + 1]);
                }
        }
        __syncthreads();
        if (s + 2 < NS)
            mg_load_stage(sb, s & 1, Ah, Al, Wh, Wl, m0, n0, (s + 2) * 32, t);
    }

    const int r4 = lane >> 2;
    const int c2 = (lane & 3) * 2;
#pragma unroll
    for (int i = 0; i < 4; i++) {
        const int grow = m0 + wm * 64 + 16 * i + r4;
#pragma unroll
        for (int j = 0; j < 4; j++) {
            const int gcol = n0 + wn * 32 + 8 * j + c2;
            const float b0 = bias[gcol], b1 = bias[gcol + 1];
            float2 v0, v1;
            v0.x = acc[i][j][0] + b0; v0.y = acc[i][j][1] + b1;
            v1.x = acc[i][j][2] + b0; v1.y = acc[i][j][3] + b1;
            *(float2*)(C + (size_t)grow * DMODEL + gcol)       = v0;
            *(float2*)(C + (size_t)(grow + 8) * DMODEL + gcol) = v1;
        }
    }
}

// ---------------- RMSNorm + RoPE -> bf16 hi/lo (dual-source) ------------------
// rows < xrows read X[row]; rows >= xrows read X2[row - xrows].
__global__ void normrope_hl(
    const float* __restrict__ X, const float* __restrict__ X2, int xrows, int rows,
    const float* __restrict__ w_txt, const float* __restrict__ w_img,
    const float* __restrict__ tcos, const float* __restrict__ tsin,
    const float* __restrict__ icos, const float* __restrict__ isin,
    float outscale,
    __nv_bfloat162* __restrict__ H, __nv_bfloat162* __restrict__ L)
{
    const int id   = blockIdx.x * blockDim.y + threadIdx.y;
    const int lane = threadIdx.x;
    if (id >= rows * NHEAD) return;
    const int row = id / NHEAD;
    const int h   = id % NHEAD;

    const float* src = (row < xrows) ? (X + (size_t)row * DMODEL)
                                     : (X2 + (size_t)(row - xrows) * DMODEL);
    const float2* p2 = (const float2*)(src + h * HD);
    float2 v0 = p2[lane];
    float2 v1 = p2[lane + 32];

    float ss = v0.x * v0.x + v0.y * v0.y + v1.x * v1.x + v1.y * v1.y;
#pragma unroll
    for (int o = 16; o > 0; o >>= 1) ss += __shfl_xor_sync(0xffffffffu, ss, o);
    const float rms = rsqrtf(ss * (1.0f / 128.0f) + 1e-6f);

    const float *w, *cT, *sT;
    if (row < STXT) { w = w_txt; cT = tcos + (size_t)row * 64;          sT = tsin + (size_t)row * 64; }
    else            { w = w_img; cT = icos + (size_t)(row - STXT) * 64; sT = isin + (size_t)(row - STXT) * 64; }

    const size_t ob = ((size_t)row * DMODEL + h * HD) / 2;
#pragma unroll
    for (int half = 0; half < 2; half++) {
        const int p = lane + 32 * half;
        const float2 v = half ? v1 : v0;
        float c = cT[p], s = sT[p];
        float yr = v.x * rms * w[2 * p];
        float yi = v.y * rms * w[2 * p + 1];
        float o0 = (yr * c - yi * s) * outscale;
        float o1 = (yr * s + yi * c) * outscale;
        __nv_bfloat16 h0 = __float2bfloat16(o0);
        __nv_bfloat16 h1 = __float2bfloat16(o1);
        __nv_bfloat16 l0 = __float2bfloat16(o0 - __bfloat162float(h0));
        __nv_bfloat16 l1 = __float2bfloat16(o1 - __bfloat162float(h1));
        H[ob + p] = __nv_bfloat162(h0, h1);
        L[ob + p] = __nv_bfloat162(l0, l1);
    }
}

// ---------------- Flash attention v3: bf16 hi/lo mma.sync --------------------
// 128q x 64kv tiles, 8 warps (16 q rows each), online softmax in registers.
#define AST     136                 // bf16 row stride (272B)
#define AMAT    (64 * AST)
#define ASTB    (AMAT * 2)          // 17408
#define ASTAGEB (4 * ASTB)          // 69632
#define ATTN3_SMEM (2 * ASTAGEB + 1024)
#define ATHREADS 256

__global__ __launch_bounds__(ATHREADS) void attn3(
    const __nv_bfloat16* __restrict__ Qh, const __nv_bfloat16* __restrict__ Ql,
    const __nv_bfloat16* __restrict__ Kh, const __nv_bfloat16* __restrict__ Kl,
    const __nv_bfloat16* __restrict__ Vh, const __nv_bfloat16* __restrict__ Vl,
    const int* __restrict__ mask,
    __nv_bfloat16* __restrict__ Oh, __nv_bfloat16* __restrict__ Ol)
{
    extern __shared__ __align__(16) char sm3[];
    const uint32_t sbase = smem_u32(sm3);
    float* mb = (float*)(sm3 + 2 * ASTAGEB);

    const int t    = threadIdx.x;
    const int wid  = t >> 5;
    const int lane = t & 31;
    const int h    = blockIdx.y;
    const int q0   = blockIdx.x * 128;
    const int hcol = h * HD;

    const int gr = lane >> 2, ct = lane & 3;
    const int mat = lane >> 3, r = lane & 7;
    const int bRow = ((mat >> 1) << 3) + r;
    const int bCol = (mat & 1) << 3;
    const int vRow = ((mat & 1) << 3) + r;
    const int vCol = (mat >> 1) << 3;

    for (int i = t; i < STXT; i += ATHREADS)
        mb[i] = (mask[i] == 0) ? -1e30f : 0.f;

    uint32_t qh[8][4], ql[8][4];
    {
        const size_t r0 = (size_t)(q0 + wid * 16 + gr) * DMODEL + hcol;
        const size_t r1 = r0 + 8 * DMODEL;
#pragma unroll
        for (int c = 0; c < 8; c++) {
            const int col = 16 * c + 2 * ct;
            qh[c][0] = *(const uint32_t*)(Qh + r0 + col);
            qh[c][1] = *(const uint32_t*)(Qh + r1 + col);
            qh[c][2] = *(const uint32_t*)(Qh + r0 + col + 8);
            qh[c][3] = *(const uint32_t*)(Qh + r1 + col + 8);
            ql[c][0] = *(const uint32_t*)(Ql + r0 + col);
            ql[c][1] = *(const uint32_t*)(Ql + r1 + col);
            ql[c][2] = *(const uint32_t*)(Ql + r0 + col + 8);
            ql[c][3] = *(const uint32_t*)(Ql + r1 + col + 8);
        }
    }

    float o[16][4];
#pragma unroll
    for (int j = 0; j < 16; j++)
#pragma unroll
        for (int e = 0; e < 4; e++) o[j][e] = 0.f;
    float m0 = -INFINITY, m1 = -INFINITY, l0 = 0.f, l1 = 0.f;

#define ISSUE_KV3(st, kb)                                                         \
    {                                                                             \
        _Pragma("unroll")                                                         \
        for (int c = t; c < 4096; c += ATHREADS) {                                \
            const int mtx = c >> 10;                                              \
            const int rem = c & 1023;                                             \
            const int row = rem >> 4;                                             \
            const int ch  = (rem & 15) * 8;                                       \
            const __nv_bfloat16* src = (mtx == 0) ? Kh : (mtx == 1) ? Kl          \
                                     : (mtx == 2) ? Vh : Vl;                      \
            cp_async16(sbase + (st) * ASTAGEB + mtx * ASTB + (row * AST + ch) * 2,\
                       src + (size_t)((kb) + row) * DMODEL + hcol + ch);          \
        }                                                                         \
        cp_commit();                                                              \
    }

    const int NT = SKV / 64;
    ISSUE_KV3(0, 0)

    for (int kt = 0; kt < NT; kt++) {
        const int kb = kt * 64;
        if (kt + 1 < NT) {
            ISSUE_KV3((kt + 1) & 1, (kt + 1) * 64)
            cp_wait<1>();
        } else {
            cp_wait<0>();
        }
        __syncthreads();
        const uint32_t stg = sbase + (kt & 1) * ASTAGEB;

        float s[8][4];
#pragma unroll
        for (int j = 0; j < 8; j++)
#pragma unroll
            for (int e = 0; e < 4; e++) s[j][e] = 0.f;

#pragma unroll
        for (int c = 0; c < 8; c++) {
#pragma unroll
            for (int g2 = 0; g2 < 4; g2++) {
                uint32_t kh0, kh1, kh2, kh3, kl0, kl1, kl2, kl3;
                const uint32_t a = stg +
                    (((g2 * 16 + bRow) * AST + 16 * c + bCol) << 1);
                LDSM_X4(kh0, kh1, kh2, kh3, a);
                LDSM_X4(kl0, kl1, kl2, kl3, a + ASTB);
                MMA16816(s[2 * g2], qh[c][0], qh[c][1], qh[c][2], qh[c][3], kh0, kh1);
                MMA16816(s[2 * g2], qh[c][0], qh[c][1], qh[c][2], qh[c][3], kl0, kl1);
                MMA16816(s[2 * g2], ql[c][0], ql[c][1], ql[c][2], ql[c][3], kh0, kh1);
                MMA16816(s[2 * g2 + 1], qh[c][0], qh[c][1], qh[c][2], qh[c][3], kh2, kh3);
                MMA16816(s[2 * g2 + 1], qh[c][0], qh[c][1], qh[c][2], qh[c][3], kl2, kl3);
                MMA16816(s[2 * g2 + 1], ql[c][0], ql[c][1], ql[c][2], ql[c][3], kh2, kh3);
            }
        }

        if (kb < STXT) {
#pragma unroll
            for (int j = 0; j < 8; j++) {
                const int col = kb + 8 * j + 2 * ct;
                const float b0 = mb[col], b1 = mb[col + 1];
                s[j][0] += b0; s[j][1] += b1;
                s[j][2] += b0; s[j][3] += b1;
            }
        }

        float tm0 = -1e30f, tm1 = -1e30f;
#pragma unroll
        for (int j = 0; j < 8; j++) {
            tm0 = fmaxf(tm0, fmaxf(s[j][0], s[j][1]));
            tm1 = fmaxf(tm1, fmaxf(s[j][2], s[j][3]));
        }
        tm0 = fmaxf(tm0, __shfl_xor_sync(0xffffffffu, tm0, 1));
        tm0 = fmaxf(tm0, __shfl_xor_sync(0xffffffffu, tm0, 2));
        tm1 = fmaxf(tm1, __shfl_xor_sync(0xffffffffu, tm1, 1));
        tm1 = fmaxf(tm1, __shfl_xor_sync(0xffffffffu, tm1, 2));
        const float mn0 = fmaxf(m0, tm0), mn1 = fmaxf(m1, tm1);
        const float c0 = __expf(m0 - mn0), c1 = __expf(m1 - mn1);
        l0 *= c0; l1 *= c1;
#pragma unroll
        for (int j = 0; j < 16; j++) {
            o[j][0] *= c0; o[j][1] *= c0;
            o[j][2] *= c1; o[j][3] *= c1;
        }
        float s0 = 0.f, s1 = 0.f;
#pragma unroll
        for (int j = 0; j < 8; j++) {
            s[j][0] = __expf(s[j][0] - mn0);
            s[j][1] = __expf(s[j][1] - mn0);
            s[j][2] = __expf(s[j][2] - mn1);
            s[j][3] = __expf(s[j][3] - mn1);
            s0 += s[j][0] + s[j][1];
            s1 += s[j][2] + s[j][3];
        }
        s0 += __shfl_xor_sync(0xffffffffu, s0, 1);
        s0 += __shfl_xor_sync(0xffffffffu, s0, 2);
        s1 += __shfl_xor_sync(0xffffffffu, s1, 1);
        s1 += __shfl_xor_sync(0xffffffffu, s1, 2);
        l0 += s0; l1 += s1;
        m0 = mn0; m1 = mn1;

        uint32_t ph[4][4], pl[4][4];
#pragma unroll
        for (int mm = 0; mm < 4; mm++) {
            const int j0 = 2 * mm, j1 = 2 * mm + 1;
            ph[mm][0] = packbf(s[j0][0], s[j0][1]);
            ph[mm][1] = packbf(s[j0][2], s[j0][3]);
            ph[mm][2] = packbf(s[j1][0], s[j1][1]);
            ph[mm][3] = packbf(s[j1][2], s[j1][3]);
            pl[mm][0] = packbf(s[j0][0] - bfhi(s[j0][0]), s[j0][1] - bfhi(s[j0][1]));
            pl[mm][1] = packbf(s[j0][2] - bfhi(s[j0][2]), s[j0][3] - bfhi(s[j0][3]));
            pl[mm][2] = packbf(s[j1][0] - bfhi(s[j1][0]), s[j1][1] - bfhi(s[j1][1]));
            pl[mm][3] = packbf(s[j1][2] - bfhi(s[j1][2]), s[j1][3] - bfhi(s[j1][3]));
        }

#pragma unroll
        for (int mm = 0; mm < 4; mm++) {
#pragma unroll
            for (int g = 0; g < 8; g++) {
                uint32_t vh0, vh1, vh2, vh3, vl0, vl1, vl2, vl3;
                const uint32_t a = stg + 2 * ASTB +
                    (((16 * mm + vRow) * AST + 16 * g + vCol) << 1);
                LDSM_X4_T(vh0, vh1, vh2, vh3, a);
                LDSM_X4_T(vl0, vl1, vl2, vl3, a + ASTB);
                MMA16816(o[2 * g], ph[mm][0], ph[mm][1], ph[mm][2], ph[mm][3], vh0, vh1);
                MMA16816(o[2 * g], ph[mm][0], ph[mm][1], ph[mm][2], ph[mm][3], vl0, vl1);
                MMA16816(o[2 * g], pl[mm][0], pl[mm][1], pl[mm][2], pl[mm][3], vh0, vh1);
                MMA16816(o[2 * g + 1], ph[mm][0], ph[mm][1], ph[mm][2], ph[mm][3], vh2, vh3);
                MMA16816(o[2 * g + 1], ph[mm][0], ph[mm][1], ph[mm][2], ph[mm][3], vl2, vl3);
                MMA16816(o[2 * g + 1], pl[mm][0], pl[mm][1], pl[mm][2], pl[mm][3], vh2, vh3);
            }
        }
        __syncthreads();
    }
#undef ISSUE_KV3

    const float inv0 = 1.0f / l0, inv1 = 1.0f / l1;
    const size_t r0 = (size_t)(q0 + wid * 16 + gr) * DMODEL + hcol;
    const size_t r1 = r0 + 8 * DMODEL;
#pragma unroll
    for (int j = 0; j < 16; j++) {
        const int col = 8 * j + 2 * ct;
        const float f0 = o[j][0] * inv0, f1 = o[j][1] * inv0;
        const float f2 = o[j][2] * inv1, f3 = o[j][3] * inv1;
        *(uint32_t*)(Oh + r0 + col) = packbf(bfhi(f0), bfhi(f1));
        *(uint32_t*)(Ol + r0 + col) = packbf(f0 - bfhi(f0), f1 - bfhi(f1));
        *(uint32_t*)(Oh + r1 + col) = packbf(bfhi(f2), bfhi(f3));
        *(uint32_t*)(Ol + r1 + col) = packbf(f2 - bfhi(f2), f3 - bfhi(f3));
    }
}

// ---------------- launch -----------------------------------------------------
extern "C" void kernel_launch(void* const* d_in, const int* in_sizes, int n_in,
                              void* d_out, int out_size)
{
    const float* hidden = (const float*)d_in[0];
    const float* enc    = (const float*)d_in[1];
    const int*   mask   = (const int*)  d_in[2];
    const float* ck     = (const float*)d_in[3];
    const float* cv     = (const float*)d_in[4];
    const float* icos   = (const float*)d_in[5];
    const float* isin   = (const float*)d_in[6];
    const float* tcos   = (const float*)d_in[7];
    const float* tsin   = (const float*)d_in[8];
    const float* Wq     = (const float*)d_in[9];
    const float* bq     = (const float*)d_in[10];
    const float* Wk     = (const float*)d_in[11];
    const float* bk     = (const float*)d_in[12];
    const float* Wv     = (const float*)d_in[13];
    const float* bv     = (const float*)d_in[14];
    const float* Wq_add = (const float*)d_in[15];
    const float* bq_add = (const float*)d_in[16];
    const float* Wk_add = (const float*)d_in[17];
    const float* bk_add = (const float*)d_in[18];
    const float* Wv_add = (const float*)d_in[19];
    const float* bv_add = (const float*)d_in[20];
    const float* nqw    = (const float*)d_in[21];
    const float* nkw    = (const float*)d_in[22];
    const float* naqw   = (const float*)d_in[23];
    const float* nakw   = (const float*)d_in[24];
    const float* Wo     = (const float*)d_in[25];
    const float* bo     = (const float*)d_in[26];
    const float* Wo_add = (const float*)d_in[27];
    const float* bo_add = (const float*)d_in[28];
    float* out = (float*)d_out;

    float *Qb, *Kb, *Vb;
    cudaGetSymbolAddress((void**)&Qb, g_Q);
    cudaGetSymbolAddress((void**)&Kb, g_K);
    cudaGetSymbolAddress((void**)&Vb, g_V);
    __nv_bfloat16 *Whb, *Wlb, *Ah, *Al, *Eh, *El, *Khb, *Klb, *Vhb, *Vlb;
    cudaGetSymbolAddress((void**)&Whb, g_Wh);
    cudaGetSymbolAddress((void**)&Wlb, g_Wl);
    cudaGetSymbolAddress((void**)&Ah, g_Ah);
    cudaGetSymbolAddress((void**)&Al, g_Al);
    cudaGetSymbolAddress((void**)&Eh, g_Eh);
    cudaGetSymbolAddress((void**)&El, g_El);
    cudaGetSymbolAddress((void**)&Khb, g_Kh);
    cudaGetSymbolAddress((void**)&Klb, g_Kl);
    cudaGetSymbolAddress((void**)&Vhb, g_Vh);
    cudaGetSymbolAddress((void**)&Vlb, g_Vl);

    cudaFuncSetAttribute(mma_gemm, cudaFuncAttributeMaxDynamicSharedMemorySize,
                         MG_SMEM);
    cudaFuncSetAttribute(attn3, cudaFuncAttributeMaxDynamicSharedMemorySize,
                         ATTN3_SMEM);

    // weight hi/lo split, native [K][N] layout (no transpose)
    {
        WSrc ws;
        ws.p[0] = Wq;     ws.p[1] = Wk;     ws.p[2] = Wv;
        ws.p[3] = Wq_add; ws.p[4] = Wk_add; ws.p[5] = Wv_add;
        ws.p[6] = Wo;     ws.p[7] = Wo_add;
        convert_hl8<<<dim3((int)(WELEMS / 4 / 256), 8), 256>>>(
            ws, (__nv_bfloat162*)Whb, (__nv_bfloat162*)Wlb);
    }
    // activation splits
    {
        int n4h = 1024 * DMODEL / 4;
        convert_hl<<<(n4h + 255) / 256, 256>>>((const float4*)hidden,
                                               (__nv_bfloat162*)Ah, (__nv_bfloat162*)Al, n4h);
        int n4e = STXT * DMODEL / 4;
        convert_hl<<<(n4e + 255) / 256, 256>>>((const float4*)enc,
                                               (__nv_bfloat162*)Eh, (__nv_bfloat162*)El, n4e);
    }

    // QKV projections: ONE launch, z=0..2 img (8 y-tiles), z=3..5 txt (2 y-tiles)
    {
        TGemmSet g;
        for (int z = 0; z < 3; z++) {
            g.ah[z] = Ah; g.al[z] = Al;
            g.wh[z] = Whb + (size_t)z * WELEMS;
            g.wl[z] = Wlb + (size_t)z * WELEMS;
            g.ny[z] = 8;
            g.ah[z + 3] = Eh; g.al[z + 3] = El;
            g.wh[z + 3] = Whb + (size_t)(z + 3) * WELEMS;
            g.wl[z + 3] = Wlb + (size_t)(z + 3) * WELEMS;
            g.ny[z + 3] = 2;
        }
        g.b[0] = bq; g.b[1] = bk; g.b[2] = bv;
        g.b[3] = bq_add; g.b[4] = bk_add; g.b[5] = bv_add;
        g.c[0] = Qb + (size_t)256 * DMODEL;
        g.c[1] = Kb + (size_t)256 * DMODEL;
        g.c[2] = Vb + (size_t)256 * DMODEL;
        g.c[3] = Qb; g.c[4] = Kb; g.c[5] = Vb;
        mma_gemm<<<dim3(24, 8, 6), 256, MG_SMEM>>>(g);
    }

    // RMSNorm + RoPE -> bf16 hi/lo
    const float qscale = 0.08838834764831845f; // 1/sqrt(128)
    dim3 nb(32, 8);
    {
        int tot = LQ * NHEAD;
        normrope_hl<<<(tot + 7) / 8, nb>>>(Qb, Qb, LQ, LQ, naqw, nqw,
                                           tcos, tsin, icos, isin, qscale,
                                           (__nv_bfloat162*)Ah, (__nv_bfloat162*)Al);
    }
    {
        // K: projected rows 0..1279 from Kb, cached rows 1280..4351 straight from ck
        int tot = SKV * NHEAD;
        normrope_hl<<<(tot + 7) / 8, nb>>>(Kb, ck, LQ, SKV, nakw, nkw,
                                           tcos, tsin, icos, isin, 1.0f,
                                           (__nv_bfloat162*)Khb, (__nv_bfloat162*)Klb);
    }
    // V hi/lo: projected rows 0..1279 + cached rows 1280..4351 (direct from cv)
    {
        int n4v = 1280 * DMODEL / 4;
        convert_hl<<<(n4v + 255) / 256, 256>>>((const float4*)Vb,
                                               (__nv_bfloat162*)Vhb, (__nv_bfloat162*)Vlb, n4v);
        int n4c = 3072 * DMODEL / 4;
        convert_hl<<<(n4c + 255) / 256, 256>>>((const float4*)cv,
                                               (__nv_bfloat162*)(Vhb + (size_t)1280 * DMODEL),
                                               (__nv_bfloat162*)(Vlb + (size_t)1280 * DMODEL), n4c);
    }

    // attention: reads Q from Ah/Al, writes O (bf16 hi/lo) back into Ah/Al
    attn3<<<dim3(LQ / 128, NHEAD), ATHREADS, ATTN3_SMEM>>>(
        Ah, Al, Khb, Klb, Vhb, Vlb, mask, Ah, Al);

    // output projections: ONE launch, z=0 img (8 y-tiles), z=1 txt (2 y-tiles)
    {
        TGemmSet g;
        g.ah[0] = Ah + (size_t)256 * DMODEL; g.al[0] = Al + (size_t)256 * DMODEL;
        g.wh[0] = Whb + 6 * WELEMS;          g.wl[0] = Wlb + 6 * WELEMS;
        g.b[0]  = bo;                        g.c[0]  = out;
        g.ny[0] = 8;
        g.ah[1] = Ah;                        g.al[1] = Al;
        g.wh[1] = Whb + 7 * WELEMS;          g.wl[1] = Wlb + 7 * WELEMS;
        g.b[1]  = bo_add;                    g.c[1]  = out + (size_t)1024 * DMODEL;
        g.ny[1] = 2;
        for (int z = 2; z < 6; z++) {
            g.ah[z] = Ah; g.al[z] = Al;
            g.wh[z] = Whb; g.wl[z] = Wlb;
            g.b[z] = bo; g.c[z] = out; g.ny[z] = 0;
        }
        mma_gemm<<<dim3(24, 8, 2), 256, MG_SMEM>>>(g);
    }
}

// round 9
// speedup vs baseline: 1.6995x; 1.5051x over previous
#include <cuda_runtime.h>
#include <cuda_bf16.h>
#include <cuda_fp16.h>
#include <math.h>
#include <stdint.h>

#define DMODEL 3072
#define NHEAD  24
#define HD     128
#define LQ     1280     // 256 txt + 1024 img queries
#define SKV    4352     // 256 txt + 1024 den + 3072 cached
#define STXT   256

// ---------------- scratch (device globals: allocation-free) ----------------
__device__ float g_Q[(size_t)LQ * DMODEL];
__device__ float g_K[(size_t)LQ * DMODEL];   // projected K rows 0..1279 only
__device__ float g_V[(size_t)LQ * DMODEL];   // projected V rows 0..1279 only

#define WELEMS ((size_t)DMODEL * DMODEL)
__device__ __half g_Wh[8 * WELEMS];                   // fp16 weights, [K][N]
__device__ __nv_bfloat16 g_Ah[(size_t)LQ * DMODEL];   // act fp16 / Q hi / O fp16
__device__ __nv_bfloat16 g_Al[(size_t)LQ * DMODEL];   // Q lo
__device__ __half g_Eh[(size_t)STXT * DMODEL];        // enc fp16
__device__ __nv_bfloat16 g_Kh[(size_t)SKV * DMODEL];
__device__ __nv_bfloat16 g_Kl[(size_t)SKV * DMODEL];
__device__ __nv_bfloat16 g_Vh[(size_t)SKV * DMODEL];
__device__ __nv_bfloat16 g_Vl[(size_t)SKV * DMODEL];

// ---------------- PTX helpers -----------------------------------------------
__device__ __forceinline__ void cp_async16(unsigned dst, const void* src) {
    asm volatile("cp.async.cg.shared.global [%0], [%1], 16;" :: "r"(dst), "l"(src));
}
__device__ __forceinline__ void cp_commit() {
    asm volatile("cp.async.commit_group;");
}
template<int N> __device__ __forceinline__ void cp_wait() {
    asm volatile("cp.async.wait_group %0;" :: "n"(N));
}
__device__ __forceinline__ uint32_t smem_u32(const void* p) {
    uint32_t a;
    asm("{ .reg .u64 t; cvta.to.shared.u64 t, %1; cvt.u32.u64 %0, t; }" : "=r"(a) : "l"(p));
    return a;
}

#define LDSM_X4(r0, r1, r2, r3, addr)                                           \
    asm volatile("ldmatrix.sync.aligned.m8n8.x4.shared.b16 {%0,%1,%2,%3}, [%4];" \
        : "=r"(r0), "=r"(r1), "=r"(r2), "=r"(r3) : "r"(addr))

#define LDSM_X4_T(r0, r1, r2, r3, addr)                                         \
    asm volatile("ldmatrix.sync.aligned.m8n8.x4.trans.shared.b16 {%0,%1,%2,%3}, [%4];" \
        : "=r"(r0), "=r"(r1), "=r"(r2), "=r"(r3) : "r"(addr))

// bf16 mma (attention)
#define MMA16816(d, a0, a1, a2, a3, b0, b1)                                     \
    asm volatile("mma.sync.aligned.m16n8k16.row.col.f32.bf16.bf16.f32 "         \
        "{%0,%1,%2,%3},{%4,%5,%6,%7},{%8,%9},{%0,%1,%2,%3};"                    \
        : "+f"((d)[0]), "+f"((d)[1]), "+f"((d)[2]), "+f"((d)[3])                \
        : "r"(a0), "r"(a1), "r"(a2), "r"(a3), "r"(b0), "r"(b1))

// fp16 mma (GEMMs)
#define MMAH16816(d, a0, a1, a2, a3, b0, b1)                                    \
    asm volatile("mma.sync.aligned.m16n8k16.row.col.f32.f16.f16.f32 "           \
        "{%0,%1,%2,%3},{%4,%5,%6,%7},{%8,%9},{%0,%1,%2,%3};"                    \
        : "+f"((d)[0]), "+f"((d)[1]), "+f"((d)[2]), "+f"((d)[3])                \
        : "r"(a0), "r"(a1), "r"(a2), "r"(a3), "r"(b0), "r"(b1))

__device__ __forceinline__ uint32_t packbf(float lo, float hi) {
    uint32_t r;
    asm("cvt.rn.bf16x2.f32 %0, %1, %2;" : "=r"(r) : "f"(hi), "f"(lo));
    return r;
}
__device__ __forceinline__ float bfhi(float x) {
    return __bfloat162float(__float2bfloat16(x));
}

// ---------------- conversion kernels ----------------------------------------
// fp32 -> fp16 single
__global__ void convert_h(const float4* __restrict__ X, __half2* __restrict__ H, int n4)
{
    int i = blockIdx.x * 256 + threadIdx.x;
    if (i >= n4) return;
    float4 v = X[i];
    H[2 * i]     = __floats2half2_rn(v.x, v.y);
    H[2 * i + 1] = __floats2half2_rn(v.z, v.w);
}

// 8 weight matrices -> fp16, native [K][N]
struct WSrc { const float* p[8]; };

__global__ void convert_h8(WSrc ws, __half2* __restrict__ H)
{
    const int mtx = blockIdx.y;
    const int i = blockIdx.x * 256 + threadIdx.x;
    const float4* __restrict__ X = (const float4*)ws.p[mtx];
    const size_t b2 = (size_t)mtx * (WELEMS / 2);
    float4 v = X[i];
    H[b2 + 2 * i]     = __floats2half2_rn(v.x, v.y);
    H[b2 + 2 * i + 1] = __floats2half2_rn(v.z, v.w);
}

// fp32 -> bf16 hi/lo (for attention K/V)
__global__ void convert_hl(const float4* __restrict__ X,
                           __nv_bfloat162* __restrict__ H,
                           __nv_bfloat162* __restrict__ L, int n4)
{
    int i = blockIdx.x * 256 + threadIdx.x;
    if (i >= n4) return;
    float4 v = X[i];
    __nv_bfloat16 h0 = __float2bfloat16(v.x);
    __nv_bfloat16 h1 = __float2bfloat16(v.y);
    __nv_bfloat16 h2 = __float2bfloat16(v.z);
    __nv_bfloat16 h3 = __float2bfloat16(v.w);
    __nv_bfloat16 l0 = __float2bfloat16(v.x - __bfloat162float(h0));
    __nv_bfloat16 l1 = __float2bfloat16(v.y - __bfloat162float(h1));
    __nv_bfloat16 l2 = __float2bfloat16(v.z - __bfloat162float(h2));
    __nv_bfloat16 l3 = __float2bfloat16(v.w - __bfloat162float(h3));
    H[2 * i]     = __nv_bfloat162(h0, h1);
    H[2 * i + 1] = __nv_bfloat162(h2, h3);
    L[2 * i]     = __nv_bfloat162(l0, l1);
    L[2 * i + 1] = __nv_bfloat162(l2, l3);
}

// ---------------- fp16 single-pass GEMM (128x128, trans-B, 4-stage) ----------
// C[z] = A[z][Mz x 3072] @ W[z][3072 x 3072] + b[z];  W stored [K][N] fp16.
struct TGemmSet {
    const __half *a[6];
    const __half *w[6];
    const float* b[6];
    float* c[6];
    int ny[6];
};

#define MG_A_BYTES      (128 * 40 * 2)        // 10240
#define MG_B_OFF        MG_A_BYTES
#define MG_STAGE_BYTES  (MG_A_BYTES + 32 * 136 * 2)   // 18944
#define MG_SMEM         (4 * MG_STAGE_BYTES)          // 75776

__device__ __forceinline__ void mg_load_stage(
    uint32_t sb, int slot,
    const __half* __restrict__ A, const __half* __restrict__ W,
    int m0, int n0, int k0, int t)
{
    const uint32_t s0 = sb + slot * MG_STAGE_BYTES;
    // A: [128 rows][32 k] -> smem [128][40]
#pragma unroll
    for (int c = t; c < 512; c += 256) {
        const int row = c >> 2;
        const int ch  = (c & 3) * 8;
        cp_async16(s0 + (row * 40 + ch) * 2,
                   A + (size_t)(m0 + row) * DMODEL + k0 + ch);
    }
    // B: [32 k-rows][128 n] -> smem [32][136]
#pragma unroll
    for (int c = t; c < 512; c += 256) {
        const int row = c >> 4;
        const int ch  = (c & 15) * 8;
        cp_async16(s0 + MG_B_OFF + (row * 136 + ch) * 2,
                   W + (size_t)(k0 + row) * DMODEL + n0 + ch);
    }
    cp_commit();
}

__global__ __launch_bounds__(256, 2) void mma_gemm(TGemmSet gs)
{
    extern __shared__ __align__(128) char smg[];
    const uint32_t sb = smem_u32(smg);

    const int z = blockIdx.z;
    if (blockIdx.y >= gs.ny[z]) return;
    const __half* __restrict__ A = gs.a[z];
    const __half* __restrict__ W = gs.w[z];
    const float* __restrict__ bias = gs.b[z];
    float* __restrict__ C = gs.c[z];

    const int t    = threadIdx.x;
    const int wid  = t >> 5;
    const int lane = t & 31;
    const int wm   = wid >> 2;        // 0..1
    const int wn   = wid & 3;         // 0..3
    const int m0   = blockIdx.y * 128;
    const int n0   = blockIdx.x * 128;

    const int mat = lane >> 3, r = lane & 7;
    int aOff[4], bOffT[2];
#pragma unroll
    for (int i = 0; i < 4; i++)
        aOff[i] = (wm * 64 + 16 * i + (mat & 1) * 8 + r) * 40 + (mat >> 1) * 8;
    {
        const int tRow = ((mat & 1) << 3) + r;   // k within 16-block
        const int tCol = (mat >> 1) << 3;        // n within 16-block
#pragma unroll
        for (int p = 0; p < 2; p++)
            bOffT[p] = tRow * 136 + wn * 32 + 16 * p + tCol;
    }

    float acc[4][4][4];
#pragma unroll
    for (int i = 0; i < 4; i++)
#pragma unroll
        for (int j = 0; j < 4; j++)
#pragma unroll
            for (int q = 0; q < 4; q++) acc[i][j][q] = 0.f;

    const int NS = DMODEL / 32;   // 96
    mg_load_stage(sb, 0, A, W, m0, n0, 0,  t);
    mg_load_stage(sb, 1, A, W, m0, n0, 32, t);
    mg_load_stage(sb, 2, A, W, m0, n0, 64, t);

    for (int s = 0; s < NS; s++) {
        cp_wait<2>();
        __syncthreads();
        const uint32_t s0 = sb + (s & 3) * MG_STAGE_BYTES;

#pragma unroll
        for (int ks = 0; ks < 2; ks++) {
            const int ke = ks * 16;
            uint32_t ah[4][4], bh[2][4];
#pragma unroll
            for (int i = 0; i < 4; i++)
                LDSM_X4(ah[i][0], ah[i][1], ah[i][2], ah[i][3],
                        s0 + (aOff[i] + ke) * 2);
#pragma unroll
            for (int p = 0; p < 2; p++)
                LDSM_X4_T(bh[p][0], bh[p][1], bh[p][2], bh[p][3],
                          s0 + MG_B_OFF + (bOffT[p] + ke * 136) * 2);
#pragma unroll
            for (int i = 0; i < 4; i++)
#pragma unroll
                for (int j = 0; j < 4; j++) {
                    const int p = j >> 1, q = (j & 1) * 2;
                    MMAH16816(acc[i][j], ah[i][0], ah[i][1], ah[i][2], ah[i][3],
                              bh[p][q], bh[p][q + 1]);
                }
        }

        // issue stage s+3 into slot (s+3)&3 (holds stage s-1, fully consumed:
        // every warp passed this iteration's __syncthreads after computing s-1).
        if (s + 3 < NS)
            mg_load_stage(sb, (s + 3) & 3, A, W, m0, n0, (s + 3) * 32, t);
        else
            cp_commit();   // empty group keeps the wait<2> accounting constant
    }

    const int r4 = lane >> 2;
    const int c2 = (lane & 3) * 2;
#pragma unroll
    for (int i = 0; i < 4; i++) {
        const int grow = m0 + wm * 64 + 16 * i + r4;
#pragma unroll
        for (int j = 0; j < 4; j++) {
            const int gcol = n0 + wn * 32 + 8 * j + c2;
            const float b0 = bias[gcol], b1 = bias[gcol + 1];
            float2 v0, v1;
            v0.x = acc[i][j][0] + b0; v0.y = acc[i][j][1] + b1;
            v1.x = acc[i][j][2] + b0; v1.y = acc[i][j][3] + b1;
            *(float2*)(C + (size_t)grow * DMODEL + gcol)       = v0;
            *(float2*)(C + (size_t)(grow + 8) * DMODEL + gcol) = v1;
        }
    }
}

// ---------------- RMSNorm + RoPE -> bf16 hi/lo (dual-source) ------------------
__global__ void normrope_hl(
    const float* __restrict__ X, const float* __restrict__ X2, int xrows, int rows,
    const float* __restrict__ w_txt, const float* __restrict__ w_img,
    const float* __restrict__ tcos, const float* __restrict__ tsin,
    const float* __restrict__ icos, const float* __restrict__ isin,
    float outscale,
    __nv_bfloat162* __restrict__ H, __nv_bfloat162* __restrict__ L)
{
    const int id   = blockIdx.x * blockDim.y + threadIdx.y;
    const int lane = threadIdx.x;
    if (id >= rows * NHEAD) return;
    const int row = id / NHEAD;
    const int h   = id % NHEAD;

    const float* src = (row < xrows) ? (X + (size_t)row * DMODEL)
                                     : (X2 + (size_t)(row - xrows) * DMODEL);
    const float2* p2 = (const float2*)(src + h * HD);
    float2 v0 = p2[lane];
    float2 v1 = p2[lane + 32];

    float ss = v0.x * v0.x + v0.y * v0.y + v1.x * v1.x + v1.y * v1.y;
#pragma unroll
    for (int o = 16; o > 0; o >>= 1) ss += __shfl_xor_sync(0xffffffffu, ss, o);
    const float rms = rsqrtf(ss * (1.0f / 128.0f) + 1e-6f);

    const float *w, *cT, *sT;
    if (row < STXT) { w = w_txt; cT = tcos + (size_t)row * 64;          sT = tsin + (size_t)row * 64; }
    else            { w = w_img; cT = icos + (size_t)(row - STXT) * 64; sT = isin + (size_t)(row - STXT) * 64; }

    const size_t ob = ((size_t)row * DMODEL + h * HD) / 2;
#pragma unroll
    for (int half = 0; half < 2; half++) {
        const int p = lane + 32 * half;
        const float2 v = half ? v1 : v0;
        float c = cT[p], s = sT[p];
        float yr = v.x * rms * w[2 * p];
        float yi = v.y * rms * w[2 * p + 1];
        float o0 = (yr * c - yi * s) * outscale;
        float o1 = (yr * s + yi * c) * outscale;
        __nv_bfloat16 h0 = __float2bfloat16(o0);
        __nv_bfloat16 h1 = __float2bfloat16(o1);
        __nv_bfloat16 l0 = __float2bfloat16(o0 - __bfloat162float(h0));
        __nv_bfloat16 l1 = __float2bfloat16(o1 - __bfloat162float(h1));
        H[ob + p] = __nv_bfloat162(h0, h1);
        L[ob + p] = __nv_bfloat162(l0, l1);
    }
}

// ---------------- Flash attention v3: bf16 hi/lo mma.sync --------------------
// 128q x 64kv tiles, 8 warps (16 q rows each), online softmax in registers.
// Epilogue writes O as fp16 (single) for the fp16 out-projection.
#define AST     136
#define AMAT    (64 * AST)
#define ASTB    (AMAT * 2)          // 17408
#define ASTAGEB (4 * ASTB)          // 69632
#define ATTN3_SMEM (2 * ASTAGEB + 1024)
#define ATHREADS 256

__global__ __launch_bounds__(ATHREADS) void attn3(
    const __nv_bfloat16* __restrict__ Qh, const __nv_bfloat16* __restrict__ Ql,
    const __nv_bfloat16* __restrict__ Kh, const __nv_bfloat16* __restrict__ Kl,
    const __nv_bfloat16* __restrict__ Vh, const __nv_bfloat16* __restrict__ Vl,
    const int* __restrict__ mask,
    __half* __restrict__ O)
{
    extern __shared__ __align__(16) char sm3[];
    const uint32_t sbase = smem_u32(sm3);
    float* mb = (float*)(sm3 + 2 * ASTAGEB);

    const int t    = threadIdx.x;
    const int wid  = t >> 5;
    const int lane = t & 31;
    const int h    = blockIdx.y;
    const int q0   = blockIdx.x * 128;
    const int hcol = h * HD;

    const int gr = lane >> 2, ct = lane & 3;
    const int mat = lane >> 3, r = lane & 7;
    const int bRow = ((mat >> 1) << 3) + r;
    const int bCol = (mat & 1) << 3;
    const int vRow = ((mat & 1) << 3) + r;
    const int vCol = (mat >> 1) << 3;

    for (int i = t; i < STXT; i += ATHREADS)
        mb[i] = (mask[i] == 0) ? -1e30f : 0.f;

    uint32_t qh[8][4], ql[8][4];
    {
        const size_t r0 = (size_t)(q0 + wid * 16 + gr) * DMODEL + hcol;
        const size_t r1 = r0 + 8 * DMODEL;
#pragma unroll
        for (int c = 0; c < 8; c++) {
            const int col = 16 * c + 2 * ct;
            qh[c][0] = *(const uint32_t*)(Qh + r0 + col);
            qh[c][1] = *(const uint32_t*)(Qh + r1 + col);
            qh[c][2] = *(const uint32_t*)(Qh + r0 + col + 8);
            qh[c][3] = *(const uint32_t*)(Qh + r1 + col + 8);
            ql[c][0] = *(const uint32_t*)(Ql + r0 + col);
            ql[c][1] = *(const uint32_t*)(Ql + r1 + col);
            ql[c][2] = *(const uint32_t*)(Ql + r0 + col + 8);
            ql[c][3] = *(const uint32_t*)(Ql + r1 + col + 8);
        }
    }

    float o[16][4];
#pragma unroll
    for (int j = 0; j < 16; j++)
#pragma unroll
        for (int e = 0; e < 4; e++) o[j][e] = 0.f;
    float m0 = -INFINITY, m1 = -INFINITY, l0 = 0.f, l1 = 0.f;

#define ISSUE_KV3(st, kb)                                                         \
    {                                                                             \
        _Pragma("unroll")                                                         \
        for (int c = t; c < 4096; c += ATHREADS) {                                \
            const int mtx = c >> 10;                                              \
            const int rem = c & 1023;                                             \
            const int row = rem >> 4;                                             \
            const int ch  = (rem & 15) * 8;                                       \
            const __nv_bfloat16* src = (mtx == 0) ? Kh : (mtx == 1) ? Kl          \
                                     : (mtx == 2) ? Vh : Vl;                      \
            cp_async16(sbase + (st) * ASTAGEB + mtx * ASTB + (row * AST + ch) * 2,\
                       src + (size_t)((kb) + row) * DMODEL + hcol + ch);          \
        }                                                                         \
        cp_commit();                                                              \
    }

    const int NT = SKV / 64;
    ISSUE_KV3(0, 0)

    for (int kt = 0; kt < NT; kt++) {
        const int kb = kt * 64;
        if (kt + 1 < NT) {
            ISSUE_KV3((kt + 1) & 1, (kt + 1) * 64)
            cp_wait<1>();
        } else {
            cp_wait<0>();
        }
        __syncthreads();
        const uint32_t stg = sbase + (kt & 1) * ASTAGEB;

        float s[8][4];
#pragma unroll
        for (int j = 0; j < 8; j++)
#pragma unroll
            for (int e = 0; e < 4; e++) s[j][e] = 0.f;

#pragma unroll
        for (int c = 0; c < 8; c++) {
#pragma unroll
            for (int g2 = 0; g2 < 4; g2++) {
                uint32_t kh0, kh1, kh2, kh3, kl0, kl1, kl2, kl3;
                const uint32_t a = stg +
                    (((g2 * 16 + bRow) * AST + 16 * c + bCol) << 1);
                LDSM_X4(kh0, kh1, kh2, kh3, a);
                LDSM_X4(kl0, kl1, kl2, kl3, a + ASTB);
                MMA16816(s[2 * g2], qh[c][0], qh[c][1], qh[c][2], qh[c][3], kh0, kh1);
                MMA16816(s[2 * g2], qh[c][0], qh[c][1], qh[c][2], qh[c][3], kl0, kl1);
                MMA16816(s[2 * g2], ql[c][0], ql[c][1], ql[c][2], ql[c][3], kh0, kh1);
                MMA16816(s[2 * g2 + 1], qh[c][0], qh[c][1], qh[c][2], qh[c][3], kh2, kh3);
                MMA16816(s[2 * g2 + 1], qh[c][0], qh[c][1], qh[c][2], qh[c][3], kl2, kl3);
                MMA16816(s[2 * g2 + 1], ql[c][0], ql[c][1], ql[c][2], ql[c][3], kh2, kh3);
            }
        }

        if (kb < STXT) {
#pragma unroll
            for (int j = 0; j < 8; j++) {
                const int col = kb + 8 * j + 2 * ct;
                const float b0 = mb[col], b1 = mb[col + 1];
                s[j][0] += b0; s[j][1] += b1;
                s[j][2] += b0; s[j][3] += b1;
            }
        }

        float tm0 = -1e30f, tm1 = -1e30f;
#pragma unroll
        for (int j = 0; j < 8; j++) {
            tm0 = fmaxf(tm0, fmaxf(s[j][0], s[j][1]));
            tm1 = fmaxf(tm1, fmaxf(s[j][2], s[j][3]));
        }
        tm0 = fmaxf(tm0, __shfl_xor_sync(0xffffffffu, tm0, 1));
        tm0 = fmaxf(tm0, __shfl_xor_sync(0xffffffffu, tm0, 2));
        tm1 = fmaxf(tm1, __shfl_xor_sync(0xffffffffu, tm1, 1));
        tm1 = fmaxf(tm1, __shfl_xor_sync(0xffffffffu, tm1, 2));
        const float mn0 = fmaxf(m0, tm0), mn1 = fmaxf(m1, tm1);
        const float c0 = __expf(m0 - mn0), c1 = __expf(m1 - mn1);
        l0 *= c0; l1 *= c1;
#pragma unroll
        for (int j = 0; j < 16; j++) {
            o[j][0] *= c0; o[j][1] *= c0;
            o[j][2] *= c1; o[j][3] *= c1;
        }
        float s0 = 0.f, s1 = 0.f;
#pragma unroll
        for (int j = 0; j < 8; j++) {
            s[j][0] = __expf(s[j][0] - mn0);
            s[j][1] = __expf(s[j][1] - mn0);
            s[j][2] = __expf(s[j][2] - mn1);
            s[j][3] = __expf(s[j][3] - mn1);
            s0 += s[j][0] + s[j][1];
            s1 += s[j][2] + s[j][3];
        }
        s0 += __shfl_xor_sync(0xffffffffu, s0, 1);
        s0 += __shfl_xor_sync(0xffffffffu, s0, 2);
        s1 += __shfl_xor_sync(0xffffffffu, s1, 1);
        s1 += __shfl_xor_sync(0xffffffffu, s1, 2);
        l0 += s0; l1 += s1;
        m0 = mn0; m1 = mn1;

        uint32_t ph[4][4], pl[4][4];
#pragma unroll
        for (int mm = 0; mm < 4; mm++) {
            const int j0 = 2 * mm, j1 = 2 * mm + 1;
            ph[mm][0] = packbf(s[j0][0], s[j0][1]);
            ph[mm][1] = packbf(s[j0][2], s[j0][3]);
            ph[mm][2] = packbf(s[j1][0], s[j1][1]);
            ph[mm][3] = packbf(s[j1][2], s[j1][3]);
            pl[mm][0] = packbf(s[j0][0] - bfhi(s[j0][0]), s[j0][1] - bfhi(s[j0][1]));
            pl[mm][1] = packbf(s[j0][2] - bfhi(s[j0][2]), s[j0][3] - bfhi(s[j0][3]));
            pl[mm][2] = packbf(s[j1][0] - bfhi(s[j1][0]), s[j1][1] - bfhi(s[j1][1]));
            pl[mm][3] = packbf(s[j1][2] - bfhi(s[j1][2]), s[j1][3] - bfhi(s[j1][3]));
        }

#pragma unroll
        for (int mm = 0; mm < 4; mm++) {
#pragma unroll
            for (int g = 0; g < 8; g++) {
                uint32_t vh0, vh1, vh2, vh3, vl0, vl1, vl2, vl3;
                const uint32_t a = stg + 2 * ASTB +
                    (((16 * mm + vRow) * AST + 16 * g + vCol) << 1);
                LDSM_X4_T(vh0, vh1, vh2, vh3, a);
                LDSM_X4_T(vl0, vl1, vl2, vl3, a + ASTB);
                MMA16816(o[2 * g], ph[mm][0], ph[mm][1], ph[mm][2], ph[mm][3], vh0, vh1);
                MMA16816(o[2 * g], ph[mm][0], ph[mm][1], ph[mm][2], ph[mm][3], vl0, vl1);
                MMA16816(o[2 * g], pl[mm][0], pl[mm][1], pl[mm][2], pl[mm][3], vh0, vh1);
                MMA16816(o[2 * g + 1], ph[mm][0], ph[mm][1], ph[mm][2], ph[mm][3], vh2, vh3);
                MMA16816(o[2 * g + 1], ph[mm][0], ph[mm][1], ph[mm][2], ph[mm][3], vl2, vl3);
                MMA16816(o[2 * g + 1], pl[mm][0], pl[mm][1], pl[mm][2], pl[mm][3], vh2, vh3);
            }
        }
        __syncthreads();
    }
#undef ISSUE_KV3

    // ---- epilogue: O /= l, write fp16 ----
    const float inv0 = 1.0f / l0, inv1 = 1.0f / l1;
    const size_t r0 = (size_t)(q0 + wid * 16 + gr) * DMODEL + hcol;
    const size_t r1 = r0 + 8 * DMODEL;
#pragma unroll
    for (int j = 0; j < 16; j++) {
        const int col = 8 * j + 2 * ct;
        *(__half2*)(O + r0 + col) = __floats2half2_rn(o[j][0] * inv0, o[j][1] * inv0);
        *(__half2*)(O + r1 + col) = __floats2half2_rn(o[j][2] * inv1, o[j][3] * inv1);
    }
}

// ---------------- launch -----------------------------------------------------
extern "C" void kernel_launch(void* const* d_in, const int* in_sizes, int n_in,
                              void* d_out, int out_size)
{
    const float* hidden = (const float*)d_in[0];
    const float* enc    = (const float*)d_in[1];
    const int*   mask   = (const int*)  d_in[2];
    const float* ck     = (const float*)d_in[3];
    const float* cv     = (const float*)d_in[4];
    const float* icos   = (const float*)d_in[5];
    const float* isin   = (const float*)d_in[6];
    const float* tcos   = (const float*)d_in[7];
    const float* tsin   = (const float*)d_in[8];
    const float* Wq     = (const float*)d_in[9];
    const float* bq     = (const float*)d_in[10];
    const float* Wk     = (const float*)d_in[11];
    const float* bk     = (const float*)d_in[12];
    const float* Wv     = (const float*)d_in[13];
    const float* bv     = (const float*)d_in[14];
    const float* Wq_add = (const float*)d_in[15];
    const float* bq_add = (const float*)d_in[16];
    const float* Wk_add = (const float*)d_in[17];
    const float* bk_add = (const float*)d_in[18];
    const float* Wv_add = (const float*)d_in[19];
    const float* bv_add = (const float*)d_in[20];
    const float* nqw    = (const float*)d_in[21];
    const float* nkw    = (const float*)d_in[22];
    const float* naqw   = (const float*)d_in[23];
    const float* nakw   = (const float*)d_in[24];
    const float* Wo     = (const float*)d_in[25];
    const float* bo     = (const float*)d_in[26];
    const float* Wo_add = (const float*)d_in[27];
    const float* bo_add = (const float*)d_in[28];
    float* out = (float*)d_out;

    float *Qb, *Kb, *Vb;
    cudaGetSymbolAddress((void**)&Qb, g_Q);
    cudaGetSymbolAddress((void**)&Kb, g_K);
    cudaGetSymbolAddress((void**)&Vb, g_V);
    __half *Whb, *EhH;
    __nv_bfloat16 *Ah, *Al, *Khb, *Klb, *Vhb, *Vlb;
    cudaGetSymbolAddress((void**)&Whb, g_Wh);
    cudaGetSymbolAddress((void**)&Ah, g_Ah);
    cudaGetSymbolAddress((void**)&Al, g_Al);
    cudaGetSymbolAddress((void**)&EhH, g_Eh);
    cudaGetSymbolAddress((void**)&Khb, g_Kh);
    cudaGetSymbolAddress((void**)&Klb, g_Kl);
    cudaGetSymbolAddress((void**)&Vhb, g_Vh);
    cudaGetSymbolAddress((void**)&Vlb, g_Vl);

    cudaFuncSetAttribute(mma_gemm, cudaFuncAttributeMaxDynamicSharedMemorySize,
                         MG_SMEM);
    cudaFuncSetAttribute(attn3, cudaFuncAttributeMaxDynamicSharedMemorySize,
                         ATTN3_SMEM);

    // weight fp16 conversion, native [K][N]
    {
        WSrc ws;
        ws.p[0] = Wq;     ws.p[1] = Wk;     ws.p[2] = Wv;
        ws.p[3] = Wq_add; ws.p[4] = Wk_add; ws.p[5] = Wv_add;
        ws.p[6] = Wo;     ws.p[7] = Wo_add;
        convert_h8<<<dim3((int)(WELEMS / 4 / 256), 8), 256>>>(ws, (__half2*)Whb);
    }
    // activation fp16 conversion (hidden into Ah region, enc into Eh)
    {
        int n4h = 1024 * DMODEL / 4;
        convert_h<<<(n4h + 255) / 256, 256>>>((const float4*)hidden, (__half2*)Ah, n4h);
        int n4e = STXT * DMODEL / 4;
        convert_h<<<(n4e + 255) / 256, 256>>>((const float4*)enc, (__half2*)EhH, n4e);
    }

    // QKV projections: ONE launch, z=0..2 img (8 y-tiles), z=3..5 txt (2 y-tiles)
    {
        TGemmSet g;
        for (int z = 0; z < 3; z++) {
            g.a[z] = (const __half*)Ah;
            g.w[z] = Whb + (size_t)z * WELEMS;
            g.ny[z] = 8;
            g.a[z + 3] = EhH;
            g.w[z + 3] = Whb + (size_t)(z + 3) * WELEMS;
            g.ny[z + 3] = 2;
        }
        g.b[0] = bq; g.b[1] = bk; g.b[2] = bv;
        g.b[3] = bq_add; g.b[4] = bk_add; g.b[5] = bv_add;
        g.c[0] = Qb + (size_t)256 * DMODEL;
        g.c[1] = Kb + (size_t)256 * DMODEL;
        g.c[2] = Vb + (size_t)256 * DMODEL;
        g.c[3] = Qb; g.c[4] = Kb; g.c[5] = Vb;
        mma_gemm<<<dim3(24, 8, 6), 256, MG_SMEM>>>(g);
    }

    // RMSNorm + RoPE -> bf16 hi/lo (Q into Ah/Al — fp16 hidden is dead now)
    const float qscale = 0.08838834764831845f; // 1/sqrt(128)
    dim3 nb(32, 8);
    {
        int tot = LQ * NHEAD;
        normrope_hl<<<(tot + 7) / 8, nb>>>(Qb, Qb, LQ, LQ, naqw, nqw,
                                           tcos, tsin, icos, isin, qscale,
                                           (__nv_bfloat162*)Ah, (__nv_bfloat162*)Al);
    }
    {
        int tot = SKV * NHEAD;
        normrope_hl<<<(tot + 7) / 8, nb>>>(Kb, ck, LQ, SKV, nakw, nkw,
                                           tcos, tsin, icos, isin, 1.0f,
                                           (__nv_bfloat162*)Khb, (__nv_bfloat162*)Klb);
    }
    // V hi/lo: projected rows 0..1279 + cached rows 1280..4351 (direct from cv)
    {
        int n4v = 1280 * DMODEL / 4;
        convert_hl<<<(n4v + 255) / 256, 256>>>((const float4*)Vb,
                                               (__nv_bfloat162*)Vhb, (__nv_bfloat162*)Vlb, n4v);
        int n4c = 3072 * DMODEL / 4;
        convert_hl<<<(n4c + 255) / 256, 256>>>((const float4*)cv,
                                               (__nv_bfloat162*)(Vhb + (size_t)1280 * DMODEL),
                                               (__nv_bfloat162*)(Vlb + (size_t)1280 * DMODEL), n4c);
    }

    // attention: reads Q (bf16 hi/lo) from Ah/Al, writes O (fp16) into Ah region
    attn3<<<dim3(LQ / 128, NHEAD), ATHREADS, ATTN3_SMEM>>>(
        Ah, Al, Khb, Klb, Vhb, Vlb, mask, (__half*)Ah);

    // output projections: ONE launch, z=0 img (8 y-tiles), z=1 txt (2 y-tiles)
    {
        TGemmSet g;
        g.a[0] = (const __half*)Ah + (size_t)256 * DMODEL;
        g.w[0] = Whb + 6 * WELEMS;
        g.b[0] = bo;      g.c[0] = out;
        g.ny[0] = 8;
        g.a[1] = (const __half*)Ah;
        g.w[1] = Whb + 7 * WELEMS;
        g.b[1] = bo_add;  g.c[1] = out + (size_t)1024 * DMODEL;
        g.ny[1] = 2;
        for (int z = 2; z < 6; z++) {
            g.a[z] = (const __half*)Ah;
            g.w[z] = Whb;
            g.b[z] = bo; g.c[z] = out; g.ny[z] = 0;
        }
        mma_gemm<<<dim3(24, 8, 2), 256, MG_SMEM>>>(g);
    }
}

// round 10
// speedup vs baseline: 2.4482x; 1.4405x over previous
#include <cuda_runtime.h>
#include <cuda_bf16.h>
#include <cuda_fp16.h>
#include <math.h>
#include <stdint.h>

#define DMODEL 3072
#define NHEAD  24
#define HD     128
#define LQ     1280     // 256 txt + 1024 img queries
#define SKV    4352     // 256 txt + 1024 den + 3072 cached
#define STXT   256

// ---------------- scratch (device globals: allocation-free) ----------------
__device__ float g_Q[(size_t)LQ * DMODEL];
__device__ float g_K[(size_t)LQ * DMODEL];   // projected K rows 0..1279 only
__device__ float g_V[(size_t)LQ * DMODEL];   // projected V rows 0..1279 only

#define WELEMS ((size_t)DMODEL * DMODEL)
__device__ __half g_Wh[8 * WELEMS];                   // fp16 weights, [K][N]
__device__ __half g_Af[(size_t)LQ * DMODEL];          // act fp16 / Q fp16 / O fp16
__device__ __half g_Ef[(size_t)STXT * DMODEL];        // enc fp16
__device__ __half g_Kf[(size_t)SKV * DMODEL];         // K fp16 (post norm+rope)
__device__ __half g_Vf[(size_t)SKV * DMODEL];         // V fp16

// ---------------- PTX helpers -----------------------------------------------
__device__ __forceinline__ void cp_async16(unsigned dst, const void* src) {
    asm volatile("cp.async.cg.shared.global [%0], [%1], 16;" :: "r"(dst), "l"(src));
}
__device__ __forceinline__ void cp_commit() {
    asm volatile("cp.async.commit_group;");
}
template<int N> __device__ __forceinline__ void cp_wait() {
    asm volatile("cp.async.wait_group %0;" :: "n"(N));
}
__device__ __forceinline__ uint32_t smem_u32(const void* p) {
    uint32_t a;
    asm("{ .reg .u64 t; cvta.to.shared.u64 t, %1; cvt.u32.u64 %0, t; }" : "=r"(a) : "l"(p));
    return a;
}

#define LDSM_X4(r0, r1, r2, r3, addr)                                           \
    asm volatile("ldmatrix.sync.aligned.m8n8.x4.shared.b16 {%0,%1,%2,%3}, [%4];" \
        : "=r"(r0), "=r"(r1), "=r"(r2), "=r"(r3) : "r"(addr))

#define LDSM_X4_T(r0, r1, r2, r3, addr)                                         \
    asm volatile("ldmatrix.sync.aligned.m8n8.x4.trans.shared.b16 {%0,%1,%2,%3}, [%4];" \
        : "=r"(r0), "=r"(r1), "=r"(r2), "=r"(r3) : "r"(addr))

// fp16 mma
#define MMAH16816(d, a0, a1, a2, a3, b0, b1)                                    \
    asm volatile("mma.sync.aligned.m16n8k16.row.col.f32.f16.f16.f32 "           \
        "{%0,%1,%2,%3},{%4,%5,%6,%7},{%8,%9},{%0,%1,%2,%3};"                    \
        : "+f"((d)[0]), "+f"((d)[1]), "+f"((d)[2]), "+f"((d)[3])                \
        : "r"(a0), "r"(a1), "r"(a2), "r"(a3), "r"(b0), "r"(b1))

__device__ __forceinline__ uint32_t packh(float lo, float hi) {
    __half2 h = __floats2half2_rn(lo, hi);
    return *(uint32_t*)&h;
}

// ---------------- conversion kernels ----------------------------------------
__global__ void convert_h(const float4* __restrict__ X, __half2* __restrict__ H, int n4)
{
    int i = blockIdx.x * 256 + threadIdx.x;
    if (i >= n4) return;
    float4 v = X[i];
    H[2 * i]     = __floats2half2_rn(v.x, v.y);
    H[2 * i + 1] = __floats2half2_rn(v.z, v.w);
}

struct WSrc { const float* p[8]; };

__global__ void convert_h8(WSrc ws, __half2* __restrict__ H)
{
    const int mtx = blockIdx.y;
    const int i = blockIdx.x * 256 + threadIdx.x;
    const float4* __restrict__ X = (const float4*)ws.p[mtx];
    const size_t b2 = (size_t)mtx * (WELEMS / 2);
    float4 v = X[i];
    H[b2 + 2 * i]     = __floats2half2_rn(v.x, v.y);
    H[b2 + 2 * i + 1] = __floats2half2_rn(v.z, v.w);
}

// ---------------- fp16 single-pass GEMM (128x128, trans-B, 4-stage) ----------
struct TGemmSet {
    const __half *a[6];
    const __half *w[6];
    const float* b[6];
    float* c[6];
    int ny[6];
};

#define MG_A_BYTES      (128 * 40 * 2)        // 10240
#define MG_B_OFF        MG_A_BYTES
#define MG_STAGE_BYTES  (MG_A_BYTES + 32 * 136 * 2)   // 18944
#define MG_SMEM         (4 * MG_STAGE_BYTES)          // 75776

__device__ __forceinline__ void mg_load_stage(
    uint32_t sb, int slot,
    const __half* __restrict__ A, const __half* __restrict__ W,
    int m0, int n0, int k0, int t)
{
    const uint32_t s0 = sb + slot * MG_STAGE_BYTES;
#pragma unroll
    for (int c = t; c < 512; c += 256) {
        const int row = c >> 2;
        const int ch  = (c & 3) * 8;
        cp_async16(s0 + (row * 40 + ch) * 2,
                   A + (size_t)(m0 + row) * DMODEL + k0 + ch);
    }
#pragma unroll
    for (int c = t; c < 512; c += 256) {
        const int row = c >> 4;
        const int ch  = (c & 15) * 8;
        cp_async16(s0 + MG_B_OFF + (row * 136 + ch) * 2,
                   W + (size_t)(k0 + row) * DMODEL + n0 + ch);
    }
    cp_commit();
}

__global__ __launch_bounds__(256, 2) void mma_gemm(TGemmSet gs)
{
    extern __shared__ __align__(128) char smg[];
    const uint32_t sb = smem_u32(smg);

    const int z = blockIdx.z;
    if (blockIdx.y >= gs.ny[z]) return;
    const __half* __restrict__ A = gs.a[z];
    const __half* __restrict__ W = gs.w[z];
    const float* __restrict__ bias = gs.b[z];
    float* __restrict__ C = gs.c[z];

    const int t    = threadIdx.x;
    const int wid  = t >> 5;
    const int lane = t & 31;
    const int wm   = wid >> 2;
    const int wn   = wid & 3;
    const int m0   = blockIdx.y * 128;
    const int n0   = blockIdx.x * 128;

    const int mat = lane >> 3, r = lane & 7;
    int aOff[4], bOffT[2];
#pragma unroll
    for (int i = 0; i < 4; i++)
        aOff[i] = (wm * 64 + 16 * i + (mat & 1) * 8 + r) * 40 + (mat >> 1) * 8;
    {
        const int tRow = ((mat & 1) << 3) + r;
        const int tCol = (mat >> 1) << 3;
#pragma unroll
        for (int p = 0; p < 2; p++)
            bOffT[p] = tRow * 136 + wn * 32 + 16 * p + tCol;
    }

    float acc[4][4][4];
#pragma unroll
    for (int i = 0; i < 4; i++)
#pragma unroll
        for (int j = 0; j < 4; j++)
#pragma unroll
            for (int q = 0; q < 4; q++) acc[i][j][q] = 0.f;

    const int NS = DMODEL / 32;   // 96
    mg_load_stage(sb, 0, A, W, m0, n0, 0,  t);
    mg_load_stage(sb, 1, A, W, m0, n0, 32, t);
    mg_load_stage(sb, 2, A, W, m0, n0, 64, t);

    for (int s = 0; s < NS; s++) {
        cp_wait<2>();
        __syncthreads();
        const uint32_t s0 = sb + (s & 3) * MG_STAGE_BYTES;

#pragma unroll
        for (int ks = 0; ks < 2; ks++) {
            const int ke = ks * 16;
            uint32_t ah[4][4], bh[2][4];
#pragma unroll
            for (int i = 0; i < 4; i++)
                LDSM_X4(ah[i][0], ah[i][1], ah[i][2], ah[i][3],
                        s0 + (aOff[i] + ke) * 2);
#pragma unroll
            for (int p = 0; p < 2; p++)
                LDSM_X4_T(bh[p][0], bh[p][1], bh[p][2], bh[p][3],
                          s0 + MG_B_OFF + (bOffT[p] + ke * 136) * 2);
#pragma unroll
            for (int i = 0; i < 4; i++)
#pragma unroll
                for (int j = 0; j < 4; j++) {
                    const int p = j >> 1, q = (j & 1) * 2;
                    MMAH16816(acc[i][j], ah[i][0], ah[i][1], ah[i][2], ah[i][3],
                              bh[p][q], bh[p][q + 1]);
                }
        }

        if (s + 3 < NS)
            mg_load_stage(sb, (s + 3) & 3, A, W, m0, n0, (s + 3) * 32, t);
        else
            cp_commit();
    }

    const int r4 = lane >> 2;
    const int c2 = (lane & 3) * 2;
#pragma unroll
    for (int i = 0; i < 4; i++) {
        const int grow = m0 + wm * 64 + 16 * i + r4;
#pragma unroll
        for (int j = 0; j < 4; j++) {
            const int gcol = n0 + wn * 32 + 8 * j + c2;
            const float b0 = bias[gcol], b1 = bias[gcol + 1];
            float2 v0, v1;
            v0.x = acc[i][j][0] + b0; v0.y = acc[i][j][1] + b1;
            v1.x = acc[i][j][2] + b0; v1.y = acc[i][j][3] + b1;
            *(float2*)(C + (size_t)grow * DMODEL + gcol)       = v0;
            *(float2*)(C + (size_t)(grow + 8) * DMODEL + gcol) = v1;
        }
    }
}

// ---------------- RMSNorm + RoPE -> fp16 (dual-source) ------------------------
__global__ void normrope_h(
    const float* __restrict__ X, const float* __restrict__ X2, int xrows, int rows,
    const float* __restrict__ w_txt, const float* __restrict__ w_img,
    const float* __restrict__ tcos, const float* __restrict__ tsin,
    const float* __restrict__ icos, const float* __restrict__ isin,
    float outscale, __half2* __restrict__ H)
{
    const int id   = blockIdx.x * blockDim.y + threadIdx.y;
    const int lane = threadIdx.x;
    if (id >= rows * NHEAD) return;
    const int row = id / NHEAD;
    const int h   = id % NHEAD;

    const float* src = (row < xrows) ? (X + (size_t)row * DMODEL)
                                     : (X2 + (size_t)(row - xrows) * DMODEL);
    const float2* p2 = (const float2*)(src + h * HD);
    float2 v0 = p2[lane];
    float2 v1 = p2[lane + 32];

    float ss = v0.x * v0.x + v0.y * v0.y + v1.x * v1.x + v1.y * v1.y;
#pragma unroll
    for (int o = 16; o > 0; o >>= 1) ss += __shfl_xor_sync(0xffffffffu, ss, o);
    const float rms = rsqrtf(ss * (1.0f / 128.0f) + 1e-6f);

    const float *w, *cT, *sT;
    if (row < STXT) { w = w_txt; cT = tcos + (size_t)row * 64;          sT = tsin + (size_t)row * 64; }
    else            { w = w_img; cT = icos + (size_t)(row - STXT) * 64; sT = isin + (size_t)(row - STXT) * 64; }

    const size_t ob = ((size_t)row * DMODEL + h * HD) / 2;
#pragma unroll
    for (int half = 0; half < 2; half++) {
        const int p = lane + 32 * half;
        const float2 v = half ? v1 : v0;
        float c = cT[p], s = sT[p];
        float yr = v.x * rms * w[2 * p];
        float yi = v.y * rms * w[2 * p + 1];
        float o0 = (yr * c - yi * s) * outscale;
        float o1 = (yr * s + yi * c) * outscale;
        H[ob + p] = __floats2half2_rn(o0, o1);
    }
}

// ---------------- Flash attention v4: fp16 single-pass mma.sync --------------
// 128q x 64kv tiles, 8 warps (16 q rows each), online softmax in registers.
#define AST     136
#define AMAT    (64 * AST)
#define ASTB    (AMAT * 2)          // 17408 bytes per matrix
#define ASTAGEB (2 * ASTB)          // Kf|Vf stage bytes (34816)
#define ATTN4_SMEM (2 * ASTAGEB + 1024)
#define ATHREADS 256

__global__ __launch_bounds__(ATHREADS) void attn4(
    const __half* __restrict__ Qf,
    const __half* __restrict__ Kf, const __half* __restrict__ Vf,
    const int* __restrict__ mask,
    __half* __restrict__ O)
{
    extern __shared__ __align__(16) char sm3[];
    const uint32_t sbase = smem_u32(sm3);
    float* mb = (float*)(sm3 + 2 * ASTAGEB);

    const int t    = threadIdx.x;
    const int wid  = t >> 5;
    const int lane = t & 31;
    const int h    = blockIdx.y;
    const int q0   = blockIdx.x * 128;
    const int hcol = h * HD;

    const int gr = lane >> 2, ct = lane & 3;
    const int mat = lane >> 3, r = lane & 7;
    const int bRow = ((mat >> 1) << 3) + r;   // K (non-trans) ldmatrix row sel
    const int bCol = (mat & 1) << 3;
    const int vRow = ((mat & 1) << 3) + r;    // V (trans) ldmatrix row sel
    const int vCol = (mat >> 1) << 3;

    for (int i = t; i < STXT; i += ATHREADS)
        mb[i] = (mask[i] == 0) ? -1e30f : 0.f;

    // Q fragments (registers, loaded once)
    uint32_t q[8][4];
    {
        const size_t r0 = (size_t)(q0 + wid * 16 + gr) * DMODEL + hcol;
        const size_t r1 = r0 + 8 * DMODEL;
#pragma unroll
        for (int c = 0; c < 8; c++) {
            const int col = 16 * c + 2 * ct;
            q[c][0] = *(const uint32_t*)(Qf + r0 + col);
            q[c][1] = *(const uint32_t*)(Qf + r1 + col);
            q[c][2] = *(const uint32_t*)(Qf + r0 + col + 8);
            q[c][3] = *(const uint32_t*)(Qf + r1 + col + 8);
        }
    }

    float o[16][4];
#pragma unroll
    for (int j = 0; j < 16; j++)
#pragma unroll
        for (int e = 0; e < 4; e++) o[j][e] = 0.f;
    float m0 = -INFINITY, m1 = -INFINITY, l0 = 0.f, l1 = 0.f;

#define ISSUE_KV4(st, kb)                                                         \
    {                                                                             \
        _Pragma("unroll")                                                         \
        for (int c = t; c < 2048; c += ATHREADS) {                                \
            const int mtx = c >> 10;                                              \
            const int rem = c & 1023;                                             \
            const int row = rem >> 4;                                             \
            const int ch  = (rem & 15) * 8;                                       \
            const __half* src = mtx ? Vf : Kf;                                    \
            cp_async16(sbase + (st) * ASTAGEB + mtx * ASTB + (row * AST + ch) * 2,\
                       src + (size_t)((kb) + row) * DMODEL + hcol + ch);          \
        }                                                                         \
        cp_commit();                                                              \
    }

    const int NT = SKV / 64;   // 68
    ISSUE_KV4(0, 0)

    for (int kt = 0; kt < NT; kt++) {
        const int kb = kt * 64;
        if (kt + 1 < NT) {
            ISSUE_KV4((kt + 1) & 1, (kt + 1) * 64)
            cp_wait<1>();
        } else {
            cp_wait<0>();
        }
        __syncthreads();
        const uint32_t stg = sbase + (kt & 1) * ASTAGEB;

        // ---- QK ----
        float s[8][4];
#pragma unroll
        for (int j = 0; j < 8; j++)
#pragma unroll
            for (int e = 0; e < 4; e++) s[j][e] = 0.f;

#pragma unroll
        for (int c = 0; c < 8; c++) {
#pragma unroll
            for (int g2 = 0; g2 < 4; g2++) {
                uint32_t k0, k1, k2, k3;
                const uint32_t a = stg +
                    (((g2 * 16 + bRow) * AST + 16 * c + bCol) << 1);
                LDSM_X4(k0, k1, k2, k3, a);
                MMAH16816(s[2 * g2],     q[c][0], q[c][1], q[c][2], q[c][3], k0, k1);
                MMAH16816(s[2 * g2 + 1], q[c][0], q[c][1], q[c][2], q[c][3], k2, k3);
            }
        }

        if (kb < STXT) {
#pragma unroll
            for (int j = 0; j < 8; j++) {
                const int col = kb + 8 * j + 2 * ct;
                const float b0 = mb[col], b1 = mb[col + 1];
                s[j][0] += b0; s[j][1] += b1;
                s[j][2] += b0; s[j][3] += b1;
            }
        }

        // ---- online softmax ----
        float tm0 = -1e30f, tm1 = -1e30f;
#pragma unroll
        for (int j = 0; j < 8; j++) {
            tm0 = fmaxf(tm0, fmaxf(s[j][0], s[j][1]));
            tm1 = fmaxf(tm1, fmaxf(s[j][2], s[j][3]));
        }
        tm0 = fmaxf(tm0, __shfl_xor_sync(0xffffffffu, tm0, 1));
        tm0 = fmaxf(tm0, __shfl_xor_sync(0xffffffffu, tm0, 2));
        tm1 = fmaxf(tm1, __shfl_xor_sync(0xffffffffu, tm1, 1));
        tm1 = fmaxf(tm1, __shfl_xor_sync(0xffffffffu, tm1, 2));
        const float mn0 = fmaxf(m0, tm0), mn1 = fmaxf(m1, tm1);
        const float c0 = __expf(m0 - mn0), c1 = __expf(m1 - mn1);
        l0 *= c0; l1 *= c1;
#pragma unroll
        for (int j = 0; j < 16; j++) {
            o[j][0] *= c0; o[j][1] *= c0;
            o[j][2] *= c1; o[j][3] *= c1;
        }
        float s0 = 0.f, s1 = 0.f;
#pragma unroll
        for (int j = 0; j < 8; j++) {
            s[j][0] = __expf(s[j][0] - mn0);
            s[j][1] = __expf(s[j][1] - mn0);
            s[j][2] = __expf(s[j][2] - mn1);
            s[j][3] = __expf(s[j][3] - mn1);
            s0 += s[j][0] + s[j][1];
            s1 += s[j][2] + s[j][3];
        }
        s0 += __shfl_xor_sync(0xffffffffu, s0, 1);
        s0 += __shfl_xor_sync(0xffffffffu, s0, 2);
        s1 += __shfl_xor_sync(0xffffffffu, s1, 1);
        s1 += __shfl_xor_sync(0xffffffffu, s1, 2);
        l0 += s0; l1 += s1;
        m0 = mn0; m1 = mn1;

        // ---- pack P to fp16 A-fragments ----
        uint32_t ph[4][4];
#pragma unroll
        for (int mm = 0; mm < 4; mm++) {
            const int j0 = 2 * mm, j1 = 2 * mm + 1;
            ph[mm][0] = packh(s[j0][0], s[j0][1]);
            ph[mm][1] = packh(s[j0][2], s[j0][3]);
            ph[mm][2] = packh(s[j1][0], s[j1][1]);
            ph[mm][3] = packh(s[j1][2], s[j1][3]);
        }

        // ---- PV ----
#pragma unroll
        for (int mm = 0; mm < 4; mm++) {
#pragma unroll
            for (int g = 0; g < 8; g++) {
                uint32_t v0, v1, v2, v3;
                const uint32_t a = stg + ASTB +
                    (((16 * mm + vRow) * AST + 16 * g + vCol) << 1);
                LDSM_X4_T(v0, v1, v2, v3, a);
                MMAH16816(o[2 * g],     ph[mm][0], ph[mm][1], ph[mm][2], ph[mm][3], v0, v1);
                MMAH16816(o[2 * g + 1], ph[mm][0], ph[mm][1], ph[mm][2], ph[mm][3], v2, v3);
            }
        }
        __syncthreads();
    }
#undef ISSUE_KV4

    // ---- epilogue: O /= l, write fp16 ----
    const float inv0 = 1.0f / l0, inv1 = 1.0f / l1;
    const size_t r0 = (size_t)(q0 + wid * 16 + gr) * DMODEL + hcol;
    const size_t r1 = r0 + 8 * DMODEL;
#pragma unroll
    for (int j = 0; j < 16; j++) {
        const int col = 8 * j + 2 * ct;
        *(__half2*)(O + r0 + col) = __floats2half2_rn(o[j][0] * inv0, o[j][1] * inv0);
        *(__half2*)(O + r1 + col) = __floats2half2_rn(o[j][2] * inv1, o[j][3] * inv1);
    }
}

// ---------------- launch -----------------------------------------------------
extern "C" void kernel_launch(void* const* d_in, const int* in_sizes, int n_in,
                              void* d_out, int out_size)
{
    const float* hidden = (const float*)d_in[0];
    const float* enc    = (const float*)d_in[1];
    const int*   mask   = (const int*)  d_in[2];
    const float* ck     = (const float*)d_in[3];
    const float* cv     = (const float*)d_in[4];
    const float* icos   = (const float*)d_in[5];
    const float* isin   = (const float*)d_in[6];
    const float* tcos   = (const float*)d_in[7];
    const float* tsin   = (const float*)d_in[8];
    const float* Wq     = (const float*)d_in[9];
    const float* bq     = (const float*)d_in[10];
    const float* Wk     = (const float*)d_in[11];
    const float* bk     = (const float*)d_in[12];
    const float* Wv     = (const float*)d_in[13];
    const float* bv     = (const float*)d_in[14];
    const float* Wq_add = (const float*)d_in[15];
    const float* bq_add = (const float*)d_in[16];
    const float* Wk_add = (const float*)d_in[17];
    const float* bk_add = (const float*)d_in[18];
    const float* Wv_add = (const float*)d_in[19];
    const float* bv_add = (const float*)d_in[20];
    const float* nqw    = (const float*)d_in[21];
    const float* nkw    = (const float*)d_in[22];
    const float* naqw   = (const float*)d_in[23];
    const float* nakw   = (const float*)d_in[24];
    const float* Wo     = (const float*)d_in[25];
    const float* bo     = (const float*)d_in[26];
    const float* Wo_add = (const float*)d_in[27];
    const float* bo_add = (const float*)d_in[28];
    float* out = (float*)d_out;

    float *Qb, *Kb, *Vb;
    cudaGetSymbolAddress((void**)&Qb, g_Q);
    cudaGetSymbolAddress((void**)&Kb, g_K);
    cudaGetSymbolAddress((void**)&Vb, g_V);
    __half *Whb, *Af, *Ef, *Kf, *Vf;
    cudaGetSymbolAddress((void**)&Whb, g_Wh);
    cudaGetSymbolAddress((void**)&Af, g_Af);
    cudaGetSymbolAddress((void**)&Ef, g_Ef);
    cudaGetSymbolAddress((void**)&Kf, g_Kf);
    cudaGetSymbolAddress((void**)&Vf, g_Vf);

    cudaFuncSetAttribute(mma_gemm, cudaFuncAttributeMaxDynamicSharedMemorySize,
                         MG_SMEM);
    cudaFuncSetAttribute(attn4, cudaFuncAttributeMaxDynamicSharedMemorySize,
                         ATTN4_SMEM);

    // weight fp16 conversion, native [K][N]
    {
        WSrc ws;
        ws.p[0] = Wq;     ws.p[1] = Wk;     ws.p[2] = Wv;
        ws.p[3] = Wq_add; ws.p[4] = Wk_add; ws.p[5] = Wv_add;
        ws.p[6] = Wo;     ws.p[7] = Wo_add;
        convert_h8<<<dim3((int)(WELEMS / 4 / 256), 8), 256>>>(ws, (__half2*)Whb);
    }
    // activation fp16 conversion
    {
        int n4h = 1024 * DMODEL / 4;
        convert_h<<<(n4h + 255) / 256, 256>>>((const float4*)hidden, (__half2*)Af, n4h);
        int n4e = STXT * DMODEL / 4;
        convert_h<<<(n4e + 255) / 256, 256>>>((const float4*)enc, (__half2*)Ef, n4e);
    }

    // QKV projections: ONE launch, z=0..2 img (8 y-tiles), z=3..5 txt (2 y-tiles)
    {
        TGemmSet g;
        for (int z = 0; z < 3; z++) {
            g.a[z] = Af;
            g.w[z] = Whb + (size_t)z * WELEMS;
            g.ny[z] = 8;
            g.a[z + 3] = Ef;
            g.w[z + 3] = Whb + (size_t)(z + 3) * WELEMS;
            g.ny[z + 3] = 2;
        }
        g.b[0] = bq; g.b[1] = bk; g.b[2] = bv;
        g.b[3] = bq_add; g.b[4] = bk_add; g.b[5] = bv_add;
        g.c[0] = Qb + (size_t)256 * DMODEL;
        g.c[1] = Kb + (size_t)256 * DMODEL;
        g.c[2] = Vb + (size_t)256 * DMODEL;
        g.c[3] = Qb; g.c[4] = Kb; g.c[5] = Vb;
        mma_gemm<<<dim3(24, 8, 6), 256, MG_SMEM>>>(g);
    }

    // RMSNorm + RoPE -> fp16 (Q into Af — fp16 hidden copy is dead now)
    const float qscale = 0.08838834764831845f; // 1/sqrt(128)
    dim3 nb(32, 8);
    {
        int tot = LQ * NHEAD;
        normrope_h<<<(tot + 7) / 8, nb>>>(Qb, Qb, LQ, LQ, naqw, nqw,
                                          tcos, tsin, icos, isin, qscale,
                                          (__half2*)Af);
    }
    {
        // K: projected rows 0..1279 from Kb, cached rows 1280..4351 from ck
        int tot = SKV * NHEAD;
        normrope_h<<<(tot + 7) / 8, nb>>>(Kb, ck, LQ, SKV, nakw, nkw,
                                          tcos, tsin, icos, isin, 1.0f,
                                          (__half2*)Kf);
    }
    // V fp16: projected rows 0..1279 + cached rows 1280..4351 (direct from cv)
    {
        int n4v = 1280 * DMODEL / 4;
        convert_h<<<(n4v + 255) / 256, 256>>>((const float4*)Vb, (__half2*)Vf, n4v);
        int n4c = 3072 * DMODEL / 4;
        convert_h<<<(n4c + 255) / 256, 256>>>((const float4*)cv,
                                              (__half2*)(Vf + (size_t)1280 * DMODEL), n4c);
    }

    // attention: reads Q fp16 from Af, writes O fp16 back into Af
    attn4<<<dim3(LQ / 128, NHEAD), ATHREADS, ATTN4_SMEM>>>(
        Af, Kf, Vf, mask, Af);

    // output projections: ONE launch, z=0 img (8 y-tiles), z=1 txt (2 y-tiles)
    {
        TGemmSet g;
        g.a[0] = Af + (size_t)256 * DMODEL;
        g.w[0] = Whb + 6 * WELEMS;
        g.b[0] = bo;      g.c[0] = out;
        g.ny[0] = 8;
        g.a[1] = Af;
        g.w[1] = Whb + 7 * WELEMS;
        g.b[1] = bo_add;  g.c[1] = out + (size_t)1024 * DMODEL;
        g.ny[1] = 2;
        for (int z = 2; z < 6; z++) {
            g.a[z] = Af;
            g.w[z] = Whb;
            g.b[z] = bo; g.c[z] = out; g.ny[z] = 0;
        }
        mma_gemm<<<dim3(24, 8, 2), 256, MG_SMEM>>>(g);
    }
}

// round 11
// speedup vs baseline: 2.8446x; 1.1619x over previous
#include <cuda_runtime.h>
#include <cuda_fp16.h>
#include <math.h>
#include <stdint.h>

#define DMODEL 3072
#define NHEAD  24
#define HD     128
#define LQ     1280     // 256 txt + 1024 img queries
#define SKV    4352     // 256 txt + 1024 den + 3072 cached
#define STXT   256

// ---------------- scratch (device globals: allocation-free) ----------------
#define WELEMS ((size_t)DMODEL * DMODEL)
__device__ __half g_Wh[8 * WELEMS];                   // fp16 weights, [K][N]
__device__ __half g_Qp[(size_t)LQ * DMODEL];          // projected Q fp16 (pre-norm)
__device__ __half g_Kp[(size_t)LQ * DMODEL];          // projected K fp16 (pre-norm)
__device__ __half g_Af[(size_t)LQ * DMODEL];          // act fp16 / normed Q / O fp16
__device__ __half g_Ef[(size_t)STXT * DMODEL];        // enc fp16
__device__ __half g_Kf[(size_t)SKV * DMODEL];         // K fp16 (post norm+rope)
__device__ __half g_Vf[(size_t)SKV * DMODEL];         // V fp16

// ---------------- PTX helpers -----------------------------------------------
__device__ __forceinline__ void cp_async16(unsigned dst, const void* src) {
    asm volatile("cp.async.cg.shared.global [%0], [%1], 16;" :: "r"(dst), "l"(src));
}
__device__ __forceinline__ void cp_commit() {
    asm volatile("cp.async.commit_group;");
}
template<int N> __device__ __forceinline__ void cp_wait() {
    asm volatile("cp.async.wait_group %0;" :: "n"(N));
}
__device__ __forceinline__ uint32_t smem_u32(const void* p) {
    uint32_t a;
    asm("{ .reg .u64 t; cvta.to.shared.u64 t, %1; cvt.u32.u64 %0, t; }" : "=r"(a) : "l"(p));
    return a;
}

#define LDSM_X4(r0, r1, r2, r3, addr)                                           \
    asm volatile("ldmatrix.sync.aligned.m8n8.x4.shared.b16 {%0,%1,%2,%3}, [%4];" \
        : "=r"(r0), "=r"(r1), "=r"(r2), "=r"(r3) : "r"(addr))

#define LDSM_X4_T(r0, r1, r2, r3, addr)                                         \
    asm volatile("ldmatrix.sync.aligned.m8n8.x4.trans.shared.b16 {%0,%1,%2,%3}, [%4];" \
        : "=r"(r0), "=r"(r1), "=r"(r2), "=r"(r3) : "r"(addr))

#define MMAH16816(d, a0, a1, a2, a3, b0, b1)                                    \
    asm volatile("mma.sync.aligned.m16n8k16.row.col.f32.f16.f16.f32 "           \
        "{%0,%1,%2,%3},{%4,%5,%6,%7},{%8,%9},{%0,%1,%2,%3};"                    \
        : "+f"((d)[0]), "+f"((d)[1]), "+f"((d)[2]), "+f"((d)[3])                \
        : "r"(a0), "r"(a1), "r"(a2), "r"(a3), "r"(b0), "r"(b1))

__device__ __forceinline__ uint32_t packh(float lo, float hi) {
    __half2 h = __floats2half2_rn(lo, hi);
    return *(uint32_t*)&h;
}

// ---------------- prep: all fp32->fp16 conversions in ONE launch -------------
// segments: 0..7 weights, 8 hidden->Af, 9 enc->Ef, 10 cached V -> Vf+1280 rows
struct PrepSet {
    const float* src[11];
    __half* dst[11];
    int n4[11];
};

__global__ void prep(PrepSet p)
{
    const int seg = blockIdx.y;
    const int i = blockIdx.x * 256 + threadIdx.x;
    if (i >= p.n4[seg]) return;
    float4 v = ((const float4*)p.src[seg])[i];
    __half2* H = (__half2*)p.dst[seg];
    H[2 * i]     = __floats2half2_rn(v.x, v.y);
    H[2 * i + 1] = __floats2half2_rn(v.z, v.w);
}

// ---------------- fp16 single-pass GEMM (128x128, trans-B, 4-stage) ----------
struct TGemmSet {
    const __half *a[6];
    const __half *w[6];
    const float* b[6];
    void* c[6];
    int ny[6];
    int hout[6];      // 1 = write fp16, 0 = write fp32
};

#define MG_A_BYTES      (128 * 40 * 2)        // 10240
#define MG_B_OFF        MG_A_BYTES
#define MG_STAGE_BYTES  (MG_A_BYTES + 32 * 136 * 2)   // 18944
#define MG_SMEM         (4 * MG_STAGE_BYTES)          // 75776

__device__ __forceinline__ void mg_load_stage(
    uint32_t sb, int slot,
    const __half* __restrict__ A, const __half* __restrict__ W,
    int m0, int n0, int k0, int t)
{
    const uint32_t s0 = sb + slot * MG_STAGE_BYTES;
#pragma unroll
    for (int c = t; c < 512; c += 256) {
        const int row = c >> 2;
        const int ch  = (c & 3) * 8;
        cp_async16(s0 + (row * 40 + ch) * 2,
                   A + (size_t)(m0 + row) * DMODEL + k0 + ch);
    }
#pragma unroll
    for (int c = t; c < 512; c += 256) {
        const int row = c >> 4;
        const int ch  = (c & 15) * 8;
        cp_async16(s0 + MG_B_OFF + (row * 136 + ch) * 2,
                   W + (size_t)(k0 + row) * DMODEL + n0 + ch);
    }
    cp_commit();
}

__global__ __launch_bounds__(256, 2) void mma_gemm(TGemmSet gs)
{
    extern __shared__ __align__(128) char smg[];
    const uint32_t sb = smem_u32(smg);

    const int z = blockIdx.z;
    if (blockIdx.y >= gs.ny[z]) return;
    const __half* __restrict__ A = gs.a[z];
    const __half* __restrict__ W = gs.w[z];
    const float* __restrict__ bias = gs.b[z];

    const int t    = threadIdx.x;
    const int wid  = t >> 5;
    const int lane = t & 31;
    const int wm   = wid >> 2;
    const int wn   = wid & 3;
    const int m0   = blockIdx.y * 128;
    const int n0   = blockIdx.x * 128;

    const int mat = lane >> 3, r = lane & 7;
    int aOff[4], bOffT[2];
#pragma unroll
    for (int i = 0; i < 4; i++)
        aOff[i] = (wm * 64 + 16 * i + (mat & 1) * 8 + r) * 40 + (mat >> 1) * 8;
    {
        const int tRow = ((mat & 1) << 3) + r;
        const int tCol = (mat >> 1) << 3;
#pragma unroll
        for (int p = 0; p < 2; p++)
            bOffT[p] = tRow * 136 + wn * 32 + 16 * p + tCol;
    }

    float acc[4][4][4];
#pragma unroll
    for (int i = 0; i < 4; i++)
#pragma unroll
        for (int j = 0; j < 4; j++)
#pragma unroll
            for (int q = 0; q < 4; q++) acc[i][j][q] = 0.f;

    const int NS = DMODEL / 32;   // 96
    mg_load_stage(sb, 0, A, W, m0, n0, 0,  t);
    mg_load_stage(sb, 1, A, W, m0, n0, 32, t);
    mg_load_stage(sb, 2, A, W, m0, n0, 64, t);

    for (int s = 0; s < NS; s++) {
        cp_wait<2>();
        __syncthreads();
        const uint32_t s0 = sb + (s & 3) * MG_STAGE_BYTES;

#pragma unroll
        for (int ks = 0; ks < 2; ks++) {
            const int ke = ks * 16;
            uint32_t ah[4][4], bh[2][4];
#pragma unroll
            for (int i = 0; i < 4; i++)
                LDSM_X4(ah[i][0], ah[i][1], ah[i][2], ah[i][3],
                        s0 + (aOff[i] + ke) * 2);
#pragma unroll
            for (int p = 0; p < 2; p++)
                LDSM_X4_T(bh[p][0], bh[p][1], bh[p][2], bh[p][3],
                          s0 + MG_B_OFF + (bOffT[p] + ke * 136) * 2);
#pragma unroll
            for (int i = 0; i < 4; i++)
#pragma unroll
                for (int j = 0; j < 4; j++) {
                    const int p = j >> 1, q = (j & 1) * 2;
                    MMAH16816(acc[i][j], ah[i][0], ah[i][1], ah[i][2], ah[i][3],
                              bh[p][q], bh[p][q + 1]);
                }
        }

        if (s + 3 < NS)
            mg_load_stage(sb, (s + 3) & 3, A, W, m0, n0, (s + 3) * 32, t);
        else
            cp_commit();
    }

    const int r4 = lane >> 2;
    const int c2 = (lane & 3) * 2;
    if (gs.hout[z]) {
        __half* C = (__half*)gs.c[z];
#pragma unroll
        for (int i = 0; i < 4; i++) {
            const int grow = m0 + wm * 64 + 16 * i + r4;
#pragma unroll
            for (int j = 0; j < 4; j++) {
                const int gcol = n0 + wn * 32 + 8 * j + c2;
                const float b0 = bias[gcol], b1 = bias[gcol + 1];
                *(__half2*)(C + (size_t)grow * DMODEL + gcol) =
                    __floats2half2_rn(acc[i][j][0] + b0, acc[i][j][1] + b1);
                *(__half2*)(C + (size_t)(grow + 8) * DMODEL + gcol) =
                    __floats2half2_rn(acc[i][j][2] + b0, acc[i][j][3] + b1);
            }
        }
    } else {
        float* C = (float*)gs.c[z];
#pragma unroll
        for (int i = 0; i < 4; i++) {
            const int grow = m0 + wm * 64 + 16 * i + r4;
#pragma unroll
            for (int j = 0; j < 4; j++) {
                const int gcol = n0 + wn * 32 + 8 * j + c2;
                const float b0 = bias[gcol], b1 = bias[gcol + 1];
                float2 v0, v1;
                v0.x = acc[i][j][0] + b0; v0.y = acc[i][j][1] + b1;
                v1.x = acc[i][j][2] + b0; v1.y = acc[i][j][3] + b1;
                *(float2*)(C + (size_t)grow * DMODEL + gcol)       = v0;
                *(float2*)(C + (size_t)(grow + 8) * DMODEL + gcol) = v1;
            }
        }
    }
}

// ---------------- fused RMSNorm + RoPE for Q and K -> fp16, ONE launch --------
// id space covers (LQ + SKV) * NHEAD rows-heads.
// rows [0, LQ): Q path — src = Qp (fp16), out = Qout, scale = qscale.
// rows [LQ, LQ+SKV): K path — src = Kp fp16 for local rows < LQ, else ck fp32.
__global__ void normrope_qk(
    const __half* __restrict__ Qp, const __half* __restrict__ Kp,
    const float* __restrict__ ck,
    const float* __restrict__ naqw, const float* __restrict__ nqw,
    const float* __restrict__ nakw, const float* __restrict__ nkw,
    const float* __restrict__ tcos, const float* __restrict__ tsin,
    const float* __restrict__ icos, const float* __restrict__ isin,
    float qscale,
    __half2* __restrict__ Qout, __half2* __restrict__ Kout)
{
    const int id   = blockIdx.x * blockDim.y + threadIdx.y;
    const int lane = threadIdx.x;
    if (id >= (LQ + SKV) * NHEAD) return;
    const int row = id / NHEAD;
    const int h   = id % NHEAD;
    const bool isQ = row < LQ;
    const int rr = isQ ? row : row - LQ;

    float2 v0, v1;
    if (isQ) {
        const __half2* p2 = (const __half2*)(Qp + (size_t)rr * DMODEL + h * HD);
        v0 = __half22float2(p2[lane]);
        v1 = __half22float2(p2[lane + 32]);
    } else if (rr < LQ) {
        const __half2* p2 = (const __half2*)(Kp + (size_t)rr * DMODEL + h * HD);
        v0 = __half22float2(p2[lane]);
        v1 = __half22float2(p2[lane + 32]);
    } else {
        const float2* p2 = (const float2*)(ck + (size_t)(rr - LQ) * DMODEL + h * HD);
        v0 = p2[lane];
        v1 = p2[lane + 32];
    }

    float ss = v0.x * v0.x + v0.y * v0.y + v1.x * v1.x + v1.y * v1.y;
#pragma unroll
    for (int o = 16; o > 0; o >>= 1) ss += __shfl_xor_sync(0xffffffffu, ss, o);
    const float rms = rsqrtf(ss * (1.0f / 128.0f) + 1e-6f);

    const float *w, *cT, *sT;
    if (rr < STXT) {
        w = isQ ? naqw : nakw;
        cT = tcos + (size_t)rr * 64; sT = tsin + (size_t)rr * 64;
    } else {
        w = isQ ? nqw : nkw;
        cT = icos + (size_t)(rr - STXT) * 64; sT = isin + (size_t)(rr - STXT) * 64;
    }
    const float outscale = isQ ? qscale : 1.0f;
    __half2* Hout = isQ ? Qout : Kout;

    const size_t ob = ((size_t)rr * DMODEL + h * HD) / 2;
#pragma unroll
    for (int half = 0; half < 2; half++) {
        const int p = lane + 32 * half;
        const float2 v = half ? v1 : v0;
        float c = cT[p], s = sT[p];
        float yr = v.x * rms * w[2 * p];
        float yi = v.y * rms * w[2 * p + 1];
        float o0 = (yr * c - yi * s) * outscale;
        float o1 = (yr * s + yi * c) * outscale;
        Hout[ob + p] = __floats2half2_rn(o0, o1);
    }
}

// ---------------- Flash attention v4: fp16 single-pass mma.sync --------------
#define AST     136
#define AMAT    (64 * AST)
#define ASTB    (AMAT * 2)          // 17408 bytes per matrix
#define ASTAGEB (2 * ASTB)          // Kf|Vf stage bytes (34816)
#define ATTN4_SMEM (2 * ASTAGEB + 1024)
#define ATHREADS 256

__global__ __launch_bounds__(ATHREADS) void attn4(
    const __half* __restrict__ Qf,
    const __half* __restrict__ Kf, const __half* __restrict__ Vf,
    const int* __restrict__ mask,
    __half* __restrict__ O)
{
    extern __shared__ __align__(16) char sm3[];
    const uint32_t sbase = smem_u32(sm3);
    float* mb = (float*)(sm3 + 2 * ASTAGEB);

    const int t    = threadIdx.x;
    const int wid  = t >> 5;
    const int lane = t & 31;
    const int h    = blockIdx.y;
    const int q0   = blockIdx.x * 128;
    const int hcol = h * HD;

    const int gr = lane >> 2, ct = lane & 3;
    const int mat = lane >> 3, r = lane & 7;
    const int bRow = ((mat >> 1) << 3) + r;
    const int bCol = (mat & 1) << 3;
    const int vRow = ((mat & 1) << 3) + r;
    const int vCol = (mat >> 1) << 3;

    for (int i = t; i < STXT; i += ATHREADS)
        mb[i] = (mask[i] == 0) ? -1e30f : 0.f;

    uint32_t q[8][4];
    {
        const size_t r0 = (size_t)(q0 + wid * 16 + gr) * DMODEL + hcol;
        const size_t r1 = r0 + 8 * DMODEL;
#pragma unroll
        for (int c = 0; c < 8; c++) {
            const int col = 16 * c + 2 * ct;
            q[c][0] = *(const uint32_t*)(Qf + r0 + col);
            q[c][1] = *(const uint32_t*)(Qf + r1 + col);
            q[c][2] = *(const uint32_t*)(Qf + r0 + col + 8);
            q[c][3] = *(const uint32_t*)(Qf + r1 + col + 8);
        }
    }

    float o[16][4];
#pragma unroll
    for (int j = 0; j < 16; j++)
#pragma unroll
        for (int e = 0; e < 4; e++) o[j][e] = 0.f;
    float m0 = -INFINITY, m1 = -INFINITY, l0 = 0.f, l1 = 0.f;

#define ISSUE_KV4(st, kb)                                                         \
    {                                                                             \
        _Pragma("unroll")                                                         \
        for (int c = t; c < 2048; c += ATHREADS) {                                \
            const int mtx = c >> 10;                                              \
            const int rem = c & 1023;                                             \
            const int row = rem >> 4;                                             \
            const int ch  = (rem & 15) * 8;                                       \
            const __half* src = mtx ? Vf : Kf;                                    \
            cp_async16(sbase + (st) * ASTAGEB + mtx * ASTB + (row * AST + ch) * 2,\
                       src + (size_t)((kb) + row) * DMODEL + hcol + ch);          \
        }                                                                         \
        cp_commit();                                                              \
    }

    const int NT = SKV / 64;
    ISSUE_KV4(0, 0)

    for (int kt = 0; kt < NT; kt++) {
        const int kb = kt * 64;
        if (kt + 1 < NT) {
            ISSUE_KV4((kt + 1) & 1, (kt + 1) * 64)
            cp_wait<1>();
        } else {
            cp_wait<0>();
        }
        __syncthreads();
        const uint32_t stg = sbase + (kt & 1) * ASTAGEB;

        float s[8][4];
#pragma unroll
        for (int j = 0; j < 8; j++)
#pragma unroll
            for (int e = 0; e < 4; e++) s[j][e] = 0.f;

#pragma unroll
        for (int c = 0; c < 8; c++) {
#pragma unroll
            for (int g2 = 0; g2 < 4; g2++) {
                uint32_t k0, k1, k2, k3;
                const uint32_t a = stg +
                    (((g2 * 16 + bRow) * AST + 16 * c + bCol) << 1);
                LDSM_X4(k0, k1, k2, k3, a);
                MMAH16816(s[2 * g2],     q[c][0], q[c][1], q[c][2], q[c][3], k0, k1);
                MMAH16816(s[2 * g2 + 1], q[c][0], q[c][1], q[c][2], q[c][3], k2, k3);
            }
        }

        if (kb < STXT) {
#pragma unroll
            for (int j = 0; j < 8; j++) {
                const int col = kb + 8 * j + 2 * ct;
                const float b0 = mb[col], b1 = mb[col + 1];
                s[j][0] += b0; s[j][1] += b1;
                s[j][2] += b0; s[j][3] += b1;
            }
        }

        float tm0 = -1e30f, tm1 = -1e30f;
#pragma unroll
        for (int j = 0; j < 8; j++) {
            tm0 = fmaxf(tm0, fmaxf(s[j][0], s[j][1]));
            tm1 = fmaxf(tm1, fmaxf(s[j][2], s[j][3]));
        }
        tm0 = fmaxf(tm0, __shfl_xor_sync(0xffffffffu, tm0, 1));
        tm0 = fmaxf(tm0, __shfl_xor_sync(0xffffffffu, tm0, 2));
        tm1 = fmaxf(tm1, __shfl_xor_sync(0xffffffffu, tm1, 1));
        tm1 = fmaxf(tm1, __shfl_xor_sync(0xffffffffu, tm1, 2));
        const float mn0 = fmaxf(m0, tm0), mn1 = fmaxf(m1, tm1);
        const float c0 = __expf(m0 - mn0), c1 = __expf(m1 - mn1);
        l0 *= c0; l1 *= c1;
#pragma unroll
        for (int j = 0; j < 16; j++) {
            o[j][0] *= c0; o[j][1] *= c0;
            o[j][2] *= c1; o[j][3] *= c1;
        }
        float s0 = 0.f, s1 = 0.f;
#pragma unroll
        for (int j = 0; j < 8; j++) {
            s[j][0] = __expf(s[j][0] - mn0);
            s[j][1] = __expf(s[j][1] - mn0);
            s[j][2] = __expf(s[j][2] - mn1);
            s[j][3] = __expf(s[j][3] - mn1);
            s0 += s[j][0] + s[j][1];
            s1 += s[j][2] + s[j][3];
        }
        s0 += __shfl_xor_sync(0xffffffffu, s0, 1);
        s0 += __shfl_xor_sync(0xffffffffu, s0, 2);
        s1 += __shfl_xor_sync(0xffffffffu, s1, 1);
        s1 += __shfl_xor_sync(0xffffffffu, s1, 2);
        l0 += s0; l1 += s1;
        m0 = mn0; m1 = mn1;

        uint32_t ph[4][4];
#pragma unroll
        for (int mm = 0; mm < 4; mm++) {
            const int j0 = 2 * mm, j1 = 2 * mm + 1;
            ph[mm][0] = packh(s[j0][0], s[j0][1]);
            ph[mm][1] = packh(s[j0][2], s[j0][3]);
            ph[mm][2] = packh(s[j1][0], s[j1][1]);
            ph[mm][3] = packh(s[j1][2], s[j1][3]);
        }

#pragma unroll
        for (int mm = 0; mm < 4; mm++) {
#pragma unroll
            for (int g = 0; g < 8; g++) {
                uint32_t v0, v1, v2, v3;
                const uint32_t a = stg + ASTB +
                    (((16 * mm + vRow) * AST + 16 * g + vCol) << 1);
                LDSM_X4_T(v0, v1, v2, v3, a);
                MMAH16816(o[2 * g],     ph[mm][0], ph[mm][1], ph[mm][2], ph[mm][3], v0, v1);
                MMAH16816(o[2 * g + 1], ph[mm][0], ph[mm][1], ph[mm][2], ph[mm][3], v2, v3);
            }
        }
        __syncthreads();
    }
#undef ISSUE_KV4

    const float inv0 = 1.0f / l0, inv1 = 1.0f / l1;
    const size_t r0 = (size_t)(q0 + wid * 16 + gr) * DMODEL + hcol;
    const size_t r1 = r0 + 8 * DMODEL;
#pragma unroll
    for (int j = 0; j < 16; j++) {
        const int col = 8 * j + 2 * ct;
        *(__half2*)(O + r0 + col) = __floats2half2_rn(o[j][0] * inv0, o[j][1] * inv0);
        *(__half2*)(O + r1 + col) = __floats2half2_rn(o[j][2] * inv1, o[j][3] * inv1);
    }
}

// ---------------- launch -----------------------------------------------------
extern "C" void kernel_launch(void* const* d_in, const int* in_sizes, int n_in,
                              void* d_out, int out_size)
{
    const float* hidden = (const float*)d_in[0];
    const float* enc    = (const float*)d_in[1];
    const int*   mask   = (const int*)  d_in[2];
    const float* ck     = (const float*)d_in[3];
    const float* cv     = (const float*)d_in[4];
    const float* icos   = (const float*)d_in[5];
    const float* isin   = (const float*)d_in[6];
    const float* tcos   = (const float*)d_in[7];
    const float* tsin   = (const float*)d_in[8];
    const float* Wq     = (const float*)d_in[9];
    const float* bq     = (const float*)d_in[10];
    const float* Wk     = (const float*)d_in[11];
    const float* bk     = (const float*)d_in[12];
    const float* Wv     = (const float*)d_in[13];
    const float* bv     = (const float*)d_in[14];
    const float* Wq_add = (const float*)d_in[15];
    const float* bq_add = (const float*)d_in[16];
    const float* Wk_add = (const float*)d_in[17];
    const float* bk_add = (const float*)d_in[18];
    const float* Wv_add = (const float*)d_in[19];
    const float* bv_add = (const float*)d_in[20];
    const float* nqw    = (const float*)d_in[21];
    const float* nkw    = (const float*)d_in[22];
    const float* naqw   = (const float*)d_in[23];
    const float* nakw   = (const float*)d_in[24];
    const float* Wo     = (const float*)d_in[25];
    const float* bo     = (const float*)d_in[26];
    const float* Wo_add = (const float*)d_in[27];
    const float* bo_add = (const float*)d_in[28];
    float* out = (float*)d_out;

    __half *Whb, *Qp, *Kp, *Af, *Ef, *Kf, *Vf;
    cudaGetSymbolAddress((void**)&Whb, g_Wh);
    cudaGetSymbolAddress((void**)&Qp, g_Qp);
    cudaGetSymbolAddress((void**)&Kp, g_Kp);
    cudaGetSymbolAddress((void**)&Af, g_Af);
    cudaGetSymbolAddress((void**)&Ef, g_Ef);
    cudaGetSymbolAddress((void**)&Kf, g_Kf);
    cudaGetSymbolAddress((void**)&Vf, g_Vf);

    cudaFuncSetAttribute(mma_gemm, cudaFuncAttributeMaxDynamicSharedMemorySize,
                         MG_SMEM);
    cudaFuncSetAttribute(attn4, cudaFuncAttributeMaxDynamicSharedMemorySize,
                         ATTN4_SMEM);

    // -------- prep: ALL fp32->fp16 conversions in one launch --------
    {
        PrepSet p;
        const float* wsrc[8] = { Wq, Wk, Wv, Wq_add, Wk_add, Wv_add, Wo, Wo_add };
        for (int i = 0; i < 8; i++) {
            p.src[i] = wsrc[i];
            p.dst[i] = Whb + (size_t)i * WELEMS;
            p.n4[i]  = (int)(WELEMS / 4);
        }
        p.src[8] = hidden; p.dst[8] = Af;                          p.n4[8] = 1024 * DMODEL / 4;
        p.src[9] = enc;    p.dst[9] = Ef;                          p.n4[9] = STXT * DMODEL / 4;
        p.src[10] = cv;    p.dst[10] = Vf + (size_t)1280 * DMODEL; p.n4[10] = 3072 * DMODEL / 4;
        prep<<<dim3((int)(WELEMS / 4 / 256), 11), 256>>>(p);
    }

    // -------- QKV projections: ONE launch, fp16 outputs --------
    {
        TGemmSet g;
        for (int z = 0; z < 3; z++) {
            g.a[z] = Af;
            g.w[z] = Whb + (size_t)z * WELEMS;
            g.ny[z] = 8;
            g.a[z + 3] = Ef;
            g.w[z + 3] = Whb + (size_t)(z + 3) * WELEMS;
            g.ny[z + 3] = 2;
        }
        g.b[0] = bq; g.b[1] = bk; g.b[2] = bv;
        g.b[3] = bq_add; g.b[4] = bk_add; g.b[5] = bv_add;
        g.c[0] = Qp + (size_t)256 * DMODEL;
        g.c[1] = Kp + (size_t)256 * DMODEL;
        g.c[2] = Vf + (size_t)256 * DMODEL;
        g.c[3] = Qp; g.c[4] = Kp; g.c[5] = Vf;
        for (int z = 0; z < 6; z++) g.hout[z] = 1;
        mma_gemm<<<dim3(24, 8, 6), 256, MG_SMEM>>>(g);
    }

    // -------- fused RMSNorm + RoPE for Q and K (one launch) --------
    {
        const float qscale = 0.08838834764831845f; // 1/sqrt(128)
        int tot = (LQ + SKV) * NHEAD;
        normrope_qk<<<(tot + 7) / 8, dim3(32, 8)>>>(
            Qp, Kp, ck, naqw, nqw, nakw, nkw,
            tcos, tsin, icos, isin, qscale,
            (__half2*)Af, (__half2*)Kf);
    }

    // -------- attention: Q from Af, O back into Af --------
    attn4<<<dim3(LQ / 128, NHEAD), ATHREADS, ATTN4_SMEM>>>(
        Af, Kf, Vf, mask, Af);

    // -------- output projections: ONE launch, fp32 outputs --------
    {
        TGemmSet g;
        g.a[0] = Af + (size_t)256 * DMODEL;
        g.w[0] = Whb + 6 * WELEMS;
        g.b[0] = bo;      g.c[0] = out;
        g.ny[0] = 8;
        g.a[1] = Af;
        g.w[1] = Whb + 7 * WELEMS;
        g.b[1] = bo_add;  g.c[1] = out + (size_t)1024 * DMODEL;
        g.ny[1] = 2;
        for (int z = 2; z < 6; z++) {
            g.a[z] = Af;
            g.w[z] = Whb;
            g.b[z] = bo; g.c[z] = out; g.ny[z] = 0;
        }
        for (int z = 0; z < 6; z++) g.hout[z] = 0;
        mma_gemm<<<dim3(24, 8, 2), 256, MG_SMEM>>>(g);
    }
}